// round 8
// baseline (speedup 1.0000x reference)
#include <cuda_runtime.h>
#include <cuda_bf16.h>

// Problem constants (fixed by the reference setup)
#define HH 240
#define WW 304
#define IN_CH 16
#define OUT_CH 32
#define CIN 18            // pos + neg + 16 features
#define CPAD 20           // padded per-pixel channel stride: [pos,neg,f0..f15,cnt,pad]
#define BB 8
#define NPIX (BB * HH * WW)          // 583680
#define NMAX (BB * 65536)            // 524288 events
#define WSIZE (3 * 3 * CIN * OUT_CH) // 5184 weights

// Scratch (device globals: no allocation allowed in kernel_launch)
__device__ float g_dense[(size_t)NPIX * CPAD];   // ~46.7 MB accumulator (+count)
__device__ float g_conv [(size_t)NPIX * OUT_CH]; // ~74.7 MB conv output
__device__ int   g_key  [NMAX];

// ---------------------------------------------------------------------------
// 0) Zero the accumulator (must happen every graph replay)
// ---------------------------------------------------------------------------
__global__ void zero_dense_kernel() {
    const size_t n4 = (size_t)NPIX * CPAD / 4;
    size_t i = (size_t)blockIdx.x * blockDim.x + threadIdx.x;
    float4* p = reinterpret_cast<float4*>(g_dense);
    if (i < n4) p[i] = make_float4(0.f, 0.f, 0.f, 0.f);
}

// ---------------------------------------------------------------------------
// 1) Scatter: per-event vector atomics into the dense grid; cache key.
//    offsets buffer may be int32 or int64 (JAX x64 off silently downcasts);
//    detect at runtime: values are positive < 2^31, so for a little-endian
//    int64 buffer the second 32-bit word is 0.
// ---------------------------------------------------------------------------
__global__ void scatter_kernel(const float* __restrict__ events,
                               const float* __restrict__ features,
                               const int* __restrict__ offsets_raw,
                               int n, int nb) {
    int i = blockIdx.x * blockDim.x + threadIdx.x;
    if (i >= n) return;

    bool is64 = (nb > 1) ? (__ldg(&offsets_raw[1]) == 0) : false;

    float4 ev = *reinterpret_cast<const float4*>(events + (size_t)i * 4);

    // batch = searchsorted(offsets, i, side='right') = #(offsets[j] <= i)
    int b = 0;
    #pragma unroll
    for (int j = 0; j < BB; j++) {
        if (j < nb) {
            long long oj = is64
                ? __ldg(reinterpret_cast<const long long*>(offsets_raw) + j)
                : (long long)__ldg(&offsets_raw[j]);
            if (oj <= (long long)i) b++;
        }
    }

    // round-half-to-even like jnp.round, then clip
    int yi = __float2int_rn(ev.y * (float)HH);
    int xi = __float2int_rn(ev.x * (float)WW);
    yi = min(max(yi, 0), HH - 1);
    xi = min(max(xi, 0), WW - 1);
    int key = (b * HH + yi) * WW + xi;
    g_key[i] = key;

    float pos = ev.w;
    float neg = 1.0f - pos;

    const float4* f = reinterpret_cast<const float4*>(features + (size_t)i * IN_CH);
    float4 f0 = f[0], f1 = f[1], f2 = f[2], f3 = f[3];

    float* d = g_dense + (size_t)key * CPAD;
    atomicAdd(reinterpret_cast<float4*>(d +  0), make_float4(pos,  neg,  f0.x, f0.y));
    atomicAdd(reinterpret_cast<float4*>(d +  4), make_float4(f0.z, f0.w, f1.x, f1.y));
    atomicAdd(reinterpret_cast<float4*>(d +  8), make_float4(f1.z, f1.w, f2.x, f2.y));
    atomicAdd(reinterpret_cast<float4*>(d + 12), make_float4(f2.z, f2.w, f3.x, f3.y));
    atomicAdd(reinterpret_cast<float4*>(d + 16), make_float4(f3.z, f3.w, 1.0f, 0.0f));
}

// ---------------------------------------------------------------------------
// 2) Normalize: dense /= max(cnt, 1)
// ---------------------------------------------------------------------------
__global__ void normalize_kernel() {
    int p = blockIdx.x * blockDim.x + threadIdx.x;
    if (p >= NPIX) return;
    float* d = g_dense + (size_t)p * CPAD;
    float4 a0 = *reinterpret_cast<float4*>(d + 0);
    float4 a1 = *reinterpret_cast<float4*>(d + 4);
    float4 a2 = *reinterpret_cast<float4*>(d + 8);
    float4 a3 = *reinterpret_cast<float4*>(d + 12);
    float4 a4 = *reinterpret_cast<float4*>(d + 16); // f14, f15, cnt, pad
    float inv = 1.0f / fmaxf(a4.z, 1.0f);
    a0.x *= inv; a0.y *= inv; a0.z *= inv; a0.w *= inv;
    a1.x *= inv; a1.y *= inv; a1.z *= inv; a1.w *= inv;
    a2.x *= inv; a2.y *= inv; a2.z *= inv; a2.w *= inv;
    a3.x *= inv; a3.y *= inv; a3.z *= inv; a3.w *= inv;
    a4.x *= inv; a4.y *= inv;
    *reinterpret_cast<float4*>(d + 0)  = a0;
    *reinterpret_cast<float4*>(d + 4)  = a1;
    *reinterpret_cast<float4*>(d + 8)  = a2;
    *reinterpret_cast<float4*>(d + 12) = a3;
    *reinterpret_cast<float4*>(d + 16) = a4;
}

// ---------------------------------------------------------------------------
// 3) Direct 3x3 conv, SAME padding, fp32. Weights HWIO in smem (broadcast LDS).
//    One thread per pixel, 32 out channels in registers.
// ---------------------------------------------------------------------------
__global__ __launch_bounds__(256) void conv_kernel(const float* __restrict__ weight) {
    __shared__ float sw[WSIZE]; // 20736 B
    for (int i = threadIdx.x; i < WSIZE; i += blockDim.x) sw[i] = weight[i];
    __syncthreads();

    int p = blockIdx.x * blockDim.x + threadIdx.x;
    if (p >= NPIX) return;

    int b   = p / (HH * WW);
    int rem = p - b * HH * WW;
    int y   = rem / WW;
    int x   = rem - y * WW;

    float acc[OUT_CH];
    #pragma unroll
    for (int oc = 0; oc < OUT_CH; oc++) acc[oc] = 0.0f;

    #pragma unroll
    for (int ky = 0; ky < 3; ky++) {
        int iy = y + ky - 1;
        if ((unsigned)iy >= (unsigned)HH) continue;
        #pragma unroll
        for (int kx = 0; kx < 3; kx++) {
            int ix = x + kx - 1;
            if ((unsigned)ix >= (unsigned)WW) continue;

            const float* in = g_dense + ((size_t)(b * HH + iy) * WW + ix) * CPAD;
            float v[CIN];
            float4 a0 = *reinterpret_cast<const float4*>(in + 0);
            float4 a1 = *reinterpret_cast<const float4*>(in + 4);
            float4 a2 = *reinterpret_cast<const float4*>(in + 8);
            float4 a3 = *reinterpret_cast<const float4*>(in + 12);
            float2 a4 = *reinterpret_cast<const float2*>(in + 16);
            v[0]=a0.x; v[1]=a0.y; v[2]=a0.z; v[3]=a0.w;
            v[4]=a1.x; v[5]=a1.y; v[6]=a1.z; v[7]=a1.w;
            v[8]=a2.x; v[9]=a2.y; v[10]=a2.z; v[11]=a2.w;
            v[12]=a3.x; v[13]=a3.y; v[14]=a3.z; v[15]=a3.w;
            v[16]=a4.x; v[17]=a4.y;

            const float* wr = sw + (ky * 3 + kx) * CIN * OUT_CH;
            #pragma unroll
            for (int c = 0; c < CIN; c++) {
                float vv = v[c];
                const float4* w4 = reinterpret_cast<const float4*>(wr + c * OUT_CH);
                #pragma unroll
                for (int q = 0; q < OUT_CH / 4; q++) {
                    float4 w = w4[q];
                    acc[q*4+0] = fmaf(vv, w.x, acc[q*4+0]);
                    acc[q*4+1] = fmaf(vv, w.y, acc[q*4+1]);
                    acc[q*4+2] = fmaf(vv, w.z, acc[q*4+2]);
                    acc[q*4+3] = fmaf(vv, w.w, acc[q*4+3]);
                }
            }
        }
    }

    float* out = g_conv + (size_t)p * OUT_CH;
    #pragma unroll
    for (int q = 0; q < OUT_CH / 4; q++) {
        *reinterpret_cast<float4*>(out + q * 4) =
            make_float4(acc[q*4+0], acc[q*4+1], acc[q*4+2], acc[q*4+3]);
    }
}

// ---------------------------------------------------------------------------
// 4) Gather: f[i] = conv[key[i]] + bias   (8 threads / event, float4 each)
// ---------------------------------------------------------------------------
__global__ void gather_kernel(const float* __restrict__ bias,
                              float* __restrict__ out, int n) {
    int t = blockIdx.x * blockDim.x + threadIdx.x;
    if (t >= n * 8) return;
    int e = t >> 3;
    int q = t & 7;
    int key = g_key[e];
    float4 v = *reinterpret_cast<const float4*>(g_conv + (size_t)key * OUT_CH + q * 4);
    float4 bb = *reinterpret_cast<const float4*>(bias + q * 4);
    v.x += bb.x; v.y += bb.y; v.z += bb.z; v.w += bb.w;
    *reinterpret_cast<float4*>(out + (size_t)e * OUT_CH + q * 4) = v;
}

// ---------------------------------------------------------------------------
extern "C" void kernel_launch(void* const* d_in, const int* in_sizes, int n_in,
                              void* d_out, int out_size) {
    // Identify inputs by element count (robust to ordering):
    //   events:   N*4   (2,097,152)
    //   features: N*16  (8,388,608)
    //   weight:   5184
    //   bias:     32
    //   offsets:  8 (elements; dtype may be int32 or int64)
    const float* events   = nullptr;
    const float* features = nullptr;
    const float* weight   = nullptr;
    const float* bias     = nullptr;
    const int*   offsets  = nullptr;
    int n = 0, nb = 0;

    // find the two large buffers
    int big0 = -1, big1 = -1;
    for (int i = 0; i < n_in; i++) {
        int s = in_sizes[i];
        if (s == WSIZE)            weight  = (const float*)d_in[i];
        else if (s == OUT_CH)      bias    = (const float*)d_in[i];
        else if (s <= 64)        { offsets = (const int*)d_in[i]; nb = s; }
        else if (big0 < 0)         big0 = i;
        else                       big1 = i;
    }
    // events has 4 cols, features 16 cols: features is the larger
    if (in_sizes[big0] > in_sizes[big1]) { int t = big0; big0 = big1; big1 = t; }
    events   = (const float*)d_in[big0];
    features = (const float*)d_in[big1];
    n = in_sizes[big0] / 4;
    if (nb > BB) nb = BB;

    const int T = 256;

    // 0) zero accumulator
    {
        size_t n4 = (size_t)NPIX * CPAD / 4;
        int blocks = (int)((n4 + T - 1) / T);
        zero_dense_kernel<<<blocks, T>>>();
    }
    // 1) scatter
    scatter_kernel<<<(n + T - 1) / T, T>>>(events, features, offsets, n, nb);
    // 2) normalize
    normalize_kernel<<<(NPIX + T - 1) / T, T>>>();
    // 3) conv
    conv_kernel<<<(NPIX + T - 1) / T, T>>>(weight);
    // 4) gather + bias
    gather_kernel<<<(n * 8 + T - 1) / T, T>>>(bias, (float*)d_out, n);
}

// round 9
// speedup vs baseline: 1.0889x; 1.0889x over previous
#include <cuda_runtime.h>
#include <cuda_bf16.h>

// Problem constants (fixed by the reference setup)
#define HH 240
#define WW 304
#define IN_CH 16
#define OUT_CH 32
#define CIN 18            // pos + neg + 16 features
#define CPAD 20           // padded per-pixel channel stride: [pos,neg,f0..f15,cnt,pad]
#define BB 8
#define NPIX (BB * HH * WW)          // 583680
#define NMAX (BB * 65536)            // 524288 events
#define WSIZE (3 * 3 * CIN * OUT_CH) // 5184 weights

// Conv tiling
#define TX 32
#define TY 8
#define HX (TX + 2)       // 34
#define HY (TY + 2)       // 10

// Scratch (device globals: no allocation allowed in kernel_launch)
__device__ float g_dense[(size_t)NPIX * CPAD];   // ~46.7 MB accumulator (+count)
__device__ float g_conv [(size_t)NPIX * OUT_CH]; // ~74.7 MB conv output
__device__ int   g_key  [NMAX];

// ---------------------------------------------------------------------------
// 0) Zero the accumulator (must happen every graph replay)
// ---------------------------------------------------------------------------
__global__ void zero_dense_kernel() {
    const size_t n4 = (size_t)NPIX * CPAD / 4;
    size_t i = (size_t)blockIdx.x * blockDim.x + threadIdx.x;
    float4* p = reinterpret_cast<float4*>(g_dense);
    if (i < n4) p[i] = make_float4(0.f, 0.f, 0.f, 0.f);
}

// ---------------------------------------------------------------------------
// 1) Scatter: per-event vector atomics into the dense grid; cache key.
//    offsets buffer may be int32 or int64 (JAX x64 off silently downcasts);
//    detect at runtime: values are positive < 2^31, so for a little-endian
//    int64 buffer the second 32-bit word is 0.
// ---------------------------------------------------------------------------
__global__ void scatter_kernel(const float* __restrict__ events,
                               const float* __restrict__ features,
                               const int* __restrict__ offsets_raw,
                               int n, int nb) {
    int i = blockIdx.x * blockDim.x + threadIdx.x;
    if (i >= n) return;

    bool is64 = (nb > 1) ? (__ldg(&offsets_raw[1]) == 0) : false;

    float4 ev = *reinterpret_cast<const float4*>(events + (size_t)i * 4);

    // batch = searchsorted(offsets, i, side='right') = #(offsets[j] <= i)
    int b = 0;
    #pragma unroll
    for (int j = 0; j < BB; j++) {
        if (j < nb) {
            long long oj = is64
                ? __ldg(reinterpret_cast<const long long*>(offsets_raw) + j)
                : (long long)__ldg(&offsets_raw[j]);
            if (oj <= (long long)i) b++;
        }
    }

    // round-half-to-even like jnp.round, then clip
    int yi = __float2int_rn(ev.y * (float)HH);
    int xi = __float2int_rn(ev.x * (float)WW);
    yi = min(max(yi, 0), HH - 1);
    xi = min(max(xi, 0), WW - 1);
    int key = (b * HH + yi) * WW + xi;
    g_key[i] = key;

    float pos = ev.w;
    float neg = 1.0f - pos;

    const float4* f = reinterpret_cast<const float4*>(features + (size_t)i * IN_CH);
    float4 f0 = f[0], f1 = f[1], f2 = f[2], f3 = f[3];

    float* d = g_dense + (size_t)key * CPAD;
    atomicAdd(reinterpret_cast<float4*>(d +  0), make_float4(pos,  neg,  f0.x, f0.y));
    atomicAdd(reinterpret_cast<float4*>(d +  4), make_float4(f0.z, f0.w, f1.x, f1.y));
    atomicAdd(reinterpret_cast<float4*>(d +  8), make_float4(f1.z, f1.w, f2.x, f2.y));
    atomicAdd(reinterpret_cast<float4*>(d + 12), make_float4(f2.z, f2.w, f3.x, f3.y));
    atomicAdd(reinterpret_cast<float4*>(d + 16), make_float4(f3.z, f3.w, 1.0f, 0.0f));
}

// ---------------------------------------------------------------------------
// 2) Conv 3x3, SAME, fp32, normalization fused into the halo load.
//    - 32x8 outputs per block (256 threads, 1 px/thread)
//    - (34x10) halo staged in smem, divided by max(cnt,1) on the way in
//    - weights (HWIO) in smem, broadcast reads
//    - packed fma.rn.f32x2 accumulators (16 x f32x2 = 32 out channels)
// ---------------------------------------------------------------------------
__global__ __launch_bounds__(256) void conv_kernel(const float* __restrict__ weight) {
    __shared__ float sw[WSIZE];                 // 20736 B
    __shared__ float st[HY * HX * CPAD];        // 27200 B  (total 47936 B)

    const int tid = threadIdx.y * TX + threadIdx.x;

    // stage weights
    for (int i = tid; i < WSIZE; i += 256) sw[i] = weight[i];

    const int b  = blockIdx.z;
    const int y0 = blockIdx.y * TY;             // tile origin (row)
    const int x0 = blockIdx.x * TX;             // tile origin (col)

    // stage halo, normalized: st[hy][hx][c] = dense / max(cnt,1), 0 outside image
    for (int h = tid; h < HY * HX; h += 256) {
        int hy = h / HX;
        int hx = h - hy * HX;
        int gy = y0 + hy - 1;
        int gx = x0 + hx - 1;
        float* s = st + (size_t)h * CPAD;
        if ((unsigned)gy < (unsigned)HH && (unsigned)gx < (unsigned)WW) {
            const float* d = g_dense + ((size_t)(b * HH + gy) * WW + gx) * CPAD;
            float4 a0 = *reinterpret_cast<const float4*>(d + 0);
            float4 a1 = *reinterpret_cast<const float4*>(d + 4);
            float4 a2 = *reinterpret_cast<const float4*>(d + 8);
            float4 a3 = *reinterpret_cast<const float4*>(d + 12);
            float4 a4 = *reinterpret_cast<const float4*>(d + 16); // f14,f15,cnt,pad
            float inv = 1.0f / fmaxf(a4.z, 1.0f);
            a0.x *= inv; a0.y *= inv; a0.z *= inv; a0.w *= inv;
            a1.x *= inv; a1.y *= inv; a1.z *= inv; a1.w *= inv;
            a2.x *= inv; a2.y *= inv; a2.z *= inv; a2.w *= inv;
            a3.x *= inv; a3.y *= inv; a3.z *= inv; a3.w *= inv;
            a4.x *= inv; a4.y *= inv; a4.z = 0.f; a4.w = 0.f;
            *reinterpret_cast<float4*>(s + 0)  = a0;
            *reinterpret_cast<float4*>(s + 4)  = a1;
            *reinterpret_cast<float4*>(s + 8)  = a2;
            *reinterpret_cast<float4*>(s + 12) = a3;
            *reinterpret_cast<float4*>(s + 16) = a4;
        } else {
            float4 z = make_float4(0.f, 0.f, 0.f, 0.f);
            *reinterpret_cast<float4*>(s + 0)  = z;
            *reinterpret_cast<float4*>(s + 4)  = z;
            *reinterpret_cast<float4*>(s + 8)  = z;
            *reinterpret_cast<float4*>(s + 12) = z;
            *reinterpret_cast<float4*>(s + 16) = z;
        }
    }
    __syncthreads();

    const int tx = threadIdx.x;
    const int ty = threadIdx.y;
    const int gx = x0 + tx;
    const int gy = y0 + ty;
    const bool valid = (gx < WW);               // gy always < HH (240 % 8 == 0)

    // 16 packed f32x2 accumulators = 32 output channels
    unsigned long long acc2[OUT_CH / 2];
    #pragma unroll
    for (int i = 0; i < OUT_CH / 2; i++) acc2[i] = 0ull;

    for (int k = 0; k < 9; k++) {               // (ky,kx) — keep as loop for I$
        int ky = k / 3;
        int kx = k - ky * 3;
        const float* in = st + (size_t)((ty + ky) * HX + (tx + kx)) * CPAD;

        float v[CIN];
        float4 a0 = *reinterpret_cast<const float4*>(in + 0);
        float4 a1 = *reinterpret_cast<const float4*>(in + 4);
        float4 a2 = *reinterpret_cast<const float4*>(in + 8);
        float4 a3 = *reinterpret_cast<const float4*>(in + 12);
        float4 a4 = *reinterpret_cast<const float4*>(in + 16);
        v[0]=a0.x;  v[1]=a0.y;  v[2]=a0.z;  v[3]=a0.w;
        v[4]=a1.x;  v[5]=a1.y;  v[6]=a1.z;  v[7]=a1.w;
        v[8]=a2.x;  v[9]=a2.y;  v[10]=a2.z; v[11]=a2.w;
        v[12]=a3.x; v[13]=a3.y; v[14]=a3.z; v[15]=a3.w;
        v[16]=a4.x; v[17]=a4.y;

        const float* wr = sw + k * (CIN * OUT_CH);
        #pragma unroll
        for (int c = 0; c < CIN; c++) {
            unsigned long long vv2;
            asm("mov.b64 %0, {%1, %1};" : "=l"(vv2) : "f"(v[c]));
            const ulonglong2* wq =
                reinterpret_cast<const ulonglong2*>(wr + c * OUT_CH);
            #pragma unroll
            for (int q = 0; q < OUT_CH / 4; q++) { // 8 x 16B = 32 floats
                ulonglong2 w = wq[q];
                asm("fma.rn.f32x2 %0, %1, %2, %0;"
                    : "+l"(acc2[q * 2 + 0]) : "l"(vv2), "l"(w.x));
                asm("fma.rn.f32x2 %0, %1, %2, %0;"
                    : "+l"(acc2[q * 2 + 1]) : "l"(vv2), "l"(w.y));
            }
        }
    }

    if (valid) {
        float* out = g_conv + ((size_t)(b * HH + gy) * WW + gx) * OUT_CH;
        #pragma unroll
        for (int q = 0; q < OUT_CH / 4; q++) {
            float2 lo = *reinterpret_cast<float2*>(&acc2[q * 2 + 0]);
            float2 hi = *reinterpret_cast<float2*>(&acc2[q * 2 + 1]);
            *reinterpret_cast<float4*>(out + q * 4) =
                make_float4(lo.x, lo.y, hi.x, hi.y);
        }
    }
}

// ---------------------------------------------------------------------------
// 3) Gather: f[i] = conv[key[i]] + bias   (8 threads / event, float4 each)
// ---------------------------------------------------------------------------
__global__ void gather_kernel(const float* __restrict__ bias,
                              float* __restrict__ out, int n) {
    int t = blockIdx.x * blockDim.x + threadIdx.x;
    if (t >= n * 8) return;
    int e = t >> 3;
    int q = t & 7;
    int key = g_key[e];
    float4 v = *reinterpret_cast<const float4*>(g_conv + (size_t)key * OUT_CH + q * 4);
    float4 bb = *reinterpret_cast<const float4*>(bias + q * 4);
    v.x += bb.x; v.y += bb.y; v.z += bb.z; v.w += bb.w;
    *reinterpret_cast<float4*>(out + (size_t)e * OUT_CH + q * 4) = v;
}

// ---------------------------------------------------------------------------
extern "C" void kernel_launch(void* const* d_in, const int* in_sizes, int n_in,
                              void* d_out, int out_size) {
    // Identify inputs by element count (robust to ordering):
    //   events: N*4, features: N*16, weight: 5184, bias: 32, offsets: 8
    const float* events   = nullptr;
    const float* features = nullptr;
    const float* weight   = nullptr;
    const float* bias     = nullptr;
    const int*   offsets  = nullptr;
    int n = 0, nb = 0;

    int big0 = -1, big1 = -1;
    for (int i = 0; i < n_in; i++) {
        int s = in_sizes[i];
        if (s == WSIZE)            weight  = (const float*)d_in[i];
        else if (s == OUT_CH)      bias    = (const float*)d_in[i];
        else if (s <= 64)        { offsets = (const int*)d_in[i]; nb = s; }
        else if (big0 < 0)         big0 = i;
        else                       big1 = i;
    }
    if (in_sizes[big0] > in_sizes[big1]) { int t = big0; big0 = big1; big1 = t; }
    events   = (const float*)d_in[big0];
    features = (const float*)d_in[big1];
    n = in_sizes[big0] / 4;
    if (nb > BB) nb = BB;

    const int T = 256;

    // 0) zero accumulator
    {
        size_t n4 = (size_t)NPIX * CPAD / 4;
        int blocks = (int)((n4 + T - 1) / T);
        zero_dense_kernel<<<blocks, T>>>();
    }
    // 1) scatter
    scatter_kernel<<<(n + T - 1) / T, T>>>(events, features, offsets, n, nb);
    // 2) conv (normalization fused into halo load)
    {
        dim3 grid((WW + TX - 1) / TX, HH / TY, BB);   // 10 x 30 x 8
        dim3 block(TX, TY);                           // 256
        conv_kernel<<<grid, block>>>(weight);
    }
    // 3) gather + bias
    gather_kernel<<<(n * 8 + T - 1) / T, T>>>(bias, (float*)d_out, n);
}

// round 10
// speedup vs baseline: 1.1897x; 1.0926x over previous
#include <cuda_runtime.h>
#include <cuda_bf16.h>

// Problem constants (fixed by the reference setup)
#define HH 240
#define WW 304
#define IN_CH 16
#define OUT_CH 32
#define CIN 18            // pos + neg + 16 features
#define CPAD 20           // dense per-pixel stride: [pos,neg,f0..f15,cnt,pad]
#define BB 8
#define NPIX (BB * HH * WW)          // 583680
#define NMAX (BB * 65536)            // 524288 events
#define WSIZE (3 * 3 * CIN * OUT_CH) // 5184 weights

// Conv (tensor-core) tiling
#define KPAD 24           // channels padded to 3 k-steps of 8
#define CINP 25           // smem pixel stride (odd -> conflict-light fragment LDS)
#define TX2 32
#define TY2 4
#define HX2 (TX2 + 2)     // 34
#define HY2 (TY2 + 2)     // 6

// Scratch (device globals: no allocation allowed in kernel_launch)
__device__ float g_dense[(size_t)NPIX * CPAD];   // ~46.7 MB accumulator (+count)
__device__ float g_conv [(size_t)NPIX * OUT_CH]; // ~74.7 MB conv output
__device__ int   g_key  [NMAX];

__device__ __forceinline__ unsigned f2tf32(float v) {
    unsigned t;
    asm("cvt.rna.tf32.f32 %0, %1;" : "=r"(t) : "f"(v));
    return t;
}

// ---------------------------------------------------------------------------
// 0) Zero the accumulator (must happen every graph replay)
// ---------------------------------------------------------------------------
__global__ void zero_dense_kernel() {
    const size_t n4 = (size_t)NPIX * CPAD / 4;
    size_t i = (size_t)blockIdx.x * blockDim.x + threadIdx.x;
    float4* p = reinterpret_cast<float4*>(g_dense);
    if (i < n4) p[i] = make_float4(0.f, 0.f, 0.f, 0.f);
}

// ---------------------------------------------------------------------------
// 1) Scatter: per-event float4 atomics into the dense grid; cache key.
//    offsets may be int32 or int64 (detected: values positive < 2^31, so for
//    little-endian int64 the second 32-bit word is 0).
// ---------------------------------------------------------------------------
__global__ void scatter_kernel(const float* __restrict__ events,
                               const float* __restrict__ features,
                               const int* __restrict__ offsets_raw,
                               int n, int nb) {
    int i = blockIdx.x * blockDim.x + threadIdx.x;
    if (i >= n) return;

    bool is64 = (nb > 1) ? (__ldg(&offsets_raw[1]) == 0) : false;

    float4 ev = *reinterpret_cast<const float4*>(events + (size_t)i * 4);

    int b = 0;
    #pragma unroll
    for (int j = 0; j < BB; j++) {
        if (j < nb) {
            long long oj = is64
                ? __ldg(reinterpret_cast<const long long*>(offsets_raw) + j)
                : (long long)__ldg(&offsets_raw[j]);
            if (oj <= (long long)i) b++;
        }
    }

    int yi = __float2int_rn(ev.y * (float)HH);
    int xi = __float2int_rn(ev.x * (float)WW);
    yi = min(max(yi, 0), HH - 1);
    xi = min(max(xi, 0), WW - 1);
    int key = (b * HH + yi) * WW + xi;
    g_key[i] = key;

    float pos = ev.w;
    float neg = 1.0f - pos;

    const float4* f = reinterpret_cast<const float4*>(features + (size_t)i * IN_CH);
    float4 f0 = f[0], f1 = f[1], f2 = f[2], f3 = f[3];

    float* d = g_dense + (size_t)key * CPAD;
    atomicAdd(reinterpret_cast<float4*>(d +  0), make_float4(pos,  neg,  f0.x, f0.y));
    atomicAdd(reinterpret_cast<float4*>(d +  4), make_float4(f0.z, f0.w, f1.x, f1.y));
    atomicAdd(reinterpret_cast<float4*>(d +  8), make_float4(f1.z, f1.w, f2.x, f2.y));
    atomicAdd(reinterpret_cast<float4*>(d + 12), make_float4(f2.z, f2.w, f3.x, f3.y));
    atomicAdd(reinterpret_cast<float4*>(d + 16), make_float4(f3.z, f3.w, 1.0f, 0.0f));
}

// ---------------------------------------------------------------------------
// 2) Conv 3x3 SAME as implicit GEMM on tensor cores (tf32 mma.sync, fp32 acc).
//    out[px, 32] = patches[px, 9*18] @ W[9*18, 32]
//    - block: 256 thr = 8 warps; tile 32x4 pixels; warp: 16 px x 32 out-ch
//    - halo (34x6) staged in smem, normalize fused, channels padded to 24,
//      pixel stride 25 floats (bank-friendly), values pre-rounded to tf32
//    - weights staged transposed [tap][n][kpad] as tf32
//    - per warp: 9 taps x 3 k-steps x 4 n-tiles = 108 mma.m16n8k8
// ---------------------------------------------------------------------------
__global__ __launch_bounds__(256) void conv_mma_kernel(const float* __restrict__ weight) {
    __shared__ float st [HY2 * HX2 * CINP];     // 20400 B
    __shared__ float swT[9 * OUT_CH * CINP];    // 28800 B

    const int tid = threadIdx.x;
    const int b  = blockIdx.z;
    const int y0 = blockIdx.y * TY2;
    const int x0 = blockIdx.x * TX2;

    // stage weights: swT[tap][n][k] = tf32(W[tap][k][n]), zero-padded k>=18
    for (int i = tid; i < 9 * OUT_CH * KPAD; i += 256) {
        int tap = i / (OUT_CH * KPAD);
        int r   = i - tap * (OUT_CH * KPAD);
        int nn  = r / KPAD;
        int k   = r - nn * KPAD;
        float v = (k < CIN) ? __ldg(&weight[(tap * CIN + k) * OUT_CH + nn]) : 0.f;
        swT[(tap * OUT_CH + nn) * CINP + k] = __uint_as_float(f2tf32(v));
    }

    // stage halo, normalized + tf32-rounded; zeros outside the image
    for (int h = tid; h < HY2 * HX2; h += 256) {
        int hy = h / HX2;
        int hx = h - hy * HX2;
        int gy = y0 + hy - 1;
        int gx = x0 + hx - 1;
        float* s = st + h * CINP;
        float v[KPAD];
        #pragma unroll
        for (int c = 0; c < KPAD; c++) v[c] = 0.f;
        if ((unsigned)gy < (unsigned)HH && (unsigned)gx < (unsigned)WW) {
            const float* d = g_dense + ((size_t)(b * HH + gy) * WW + gx) * CPAD;
            float4 a0 = *reinterpret_cast<const float4*>(d + 0);
            float4 a1 = *reinterpret_cast<const float4*>(d + 4);
            float4 a2 = *reinterpret_cast<const float4*>(d + 8);
            float4 a3 = *reinterpret_cast<const float4*>(d + 12);
            float4 a4 = *reinterpret_cast<const float4*>(d + 16); // f14,f15,cnt,pad
            float inv = 1.0f / fmaxf(a4.z, 1.0f);
            v[0]=a0.x*inv;  v[1]=a0.y*inv;  v[2]=a0.z*inv;  v[3]=a0.w*inv;
            v[4]=a1.x*inv;  v[5]=a1.y*inv;  v[6]=a1.z*inv;  v[7]=a1.w*inv;
            v[8]=a2.x*inv;  v[9]=a2.y*inv;  v[10]=a2.z*inv; v[11]=a2.w*inv;
            v[12]=a3.x*inv; v[13]=a3.y*inv; v[14]=a3.z*inv; v[15]=a3.w*inv;
            v[16]=a4.x*inv; v[17]=a4.y*inv;
        }
        #pragma unroll
        for (int c = 0; c < KPAD; c++)
            s[c] = __uint_as_float(f2tf32(v[c]));
    }
    __syncthreads();

    const int warp = tid >> 5;
    const int lane = tid & 31;
    const int gid  = lane >> 2;   // 0..7
    const int t4   = lane & 3;    // 0..3

    const int ylocal = warp >> 1;        // 0..3
    const int xlocal = (warp & 1) * 16;  // 0 or 16

    float acc[4][4];
    #pragma unroll
    for (int nt = 0; nt < 4; nt++)
        #pragma unroll
        for (int r = 0; r < 4; r++) acc[nt][r] = 0.f;

    #pragma unroll
    for (int tap = 0; tap < 9; tap++) {
        const int ky = tap / 3;
        const int kx = tap - ky * 3;
        const float* abase = st + ((ylocal + ky) * HX2 + xlocal + kx) * CINP;
        #pragma unroll
        for (int ks = 0; ks < 3; ks++) {
            const int kb = ks * 8;
            // A fragment (16 px x 8 k), row-major
            unsigned a0 = __float_as_uint(abase[(gid    ) * CINP + kb + t4    ]);
            unsigned a1 = __float_as_uint(abase[(gid + 8) * CINP + kb + t4    ]);
            unsigned a2 = __float_as_uint(abase[(gid    ) * CINP + kb + t4 + 4]);
            unsigned a3 = __float_as_uint(abase[(gid + 8) * CINP + kb + t4 + 4]);
            #pragma unroll
            for (int nt = 0; nt < 4; nt++) {
                const float* bb = swT + (tap * OUT_CH + nt * 8 + gid) * CINP + kb + t4;
                unsigned b0 = __float_as_uint(bb[0]);
                unsigned b1 = __float_as_uint(bb[4]);
                asm volatile(
                    "mma.sync.aligned.m16n8k8.row.col.f32.tf32.tf32.f32 "
                    "{%0,%1,%2,%3}, {%4,%5,%6,%7}, {%8,%9}, {%0,%1,%2,%3};"
                    : "+f"(acc[nt][0]), "+f"(acc[nt][1]),
                      "+f"(acc[nt][2]), "+f"(acc[nt][3])
                    : "r"(a0), "r"(a1), "r"(a2), "r"(a3), "r"(b0), "r"(b1));
            }
        }
    }

    // epilogue: D[row=pixel][col=out_ch]
    const int prow = y0 + ylocal;
    const int p1 = x0 + xlocal + gid;
    const int p2 = p1 + 8;
    #pragma unroll
    for (int nt = 0; nt < 4; nt++) {
        int col = nt * 8 + t4 * 2;
        if (p1 < WW)
            *reinterpret_cast<float2*>(
                g_conv + ((size_t)(b * HH + prow) * WW + p1) * OUT_CH + col) =
                make_float2(acc[nt][0], acc[nt][1]);
        if (p2 < WW)
            *reinterpret_cast<float2*>(
                g_conv + ((size_t)(b * HH + prow) * WW + p2) * OUT_CH + col) =
                make_float2(acc[nt][2], acc[nt][3]);
    }
}

// ---------------------------------------------------------------------------
// 3) Gather: f[i] = conv[key[i]] + bias   (8 threads / event, float4 each)
// ---------------------------------------------------------------------------
__global__ void gather_kernel(const float* __restrict__ bias,
                              float* __restrict__ out, int n) {
    int t = blockIdx.x * blockDim.x + threadIdx.x;
    if (t >= n * 8) return;
    int e = t >> 3;
    int q = t & 7;
    int key = g_key[e];
    float4 v = *reinterpret_cast<const float4*>(g_conv + (size_t)key * OUT_CH + q * 4);
    float4 bb = *reinterpret_cast<const float4*>(bias + q * 4);
    v.x += bb.x; v.y += bb.y; v.z += bb.z; v.w += bb.w;
    *reinterpret_cast<float4*>(out + (size_t)e * OUT_CH + q * 4) = v;
}

// ---------------------------------------------------------------------------
extern "C" void kernel_launch(void* const* d_in, const int* in_sizes, int n_in,
                              void* d_out, int out_size) {
    // Identify inputs by element count (robust to ordering):
    //   events: N*4, features: N*16, weight: 5184, bias: 32, offsets: 8
    const float* events   = nullptr;
    const float* features = nullptr;
    const float* weight   = nullptr;
    const float* bias     = nullptr;
    const int*   offsets  = nullptr;
    int n = 0, nb = 0;

    int big0 = -1, big1 = -1;
    for (int i = 0; i < n_in; i++) {
        int s = in_sizes[i];
        if (s == WSIZE)            weight  = (const float*)d_in[i];
        else if (s == OUT_CH)      bias    = (const float*)d_in[i];
        else if (s <= 64)        { offsets = (const int*)d_in[i]; nb = s; }
        else if (big0 < 0)         big0 = i;
        else                       big1 = i;
    }
    if (in_sizes[big0] > in_sizes[big1]) { int t = big0; big0 = big1; big1 = t; }
    events   = (const float*)d_in[big0];
    features = (const float*)d_in[big1];
    n = in_sizes[big0] / 4;
    if (nb > BB) nb = BB;

    const int T = 256;

    // 0) zero accumulator
    {
        size_t n4 = (size_t)NPIX * CPAD / 4;
        int blocks = (int)((n4 + T - 1) / T);
        zero_dense_kernel<<<blocks, T>>>();
    }
    // 1) scatter
    scatter_kernel<<<(n + T - 1) / T, T>>>(events, features, offsets, n, nb);
    // 2) conv on tensor cores (normalization fused into halo staging)
    {
        dim3 grid((WW + TX2 - 1) / TX2, HH / TY2, BB);  // 10 x 60 x 8
        conv_mma_kernel<<<grid, 256>>>(weight);
    }
    // 3) gather + bias
    gather_kernel<<<(n * 8 + T - 1) / T, T>>>(bias, (float*)d_out, n);
}

// round 12
// speedup vs baseline: 1.6536x; 1.3899x over previous
#include <cuda_runtime.h>
#include <cuda_fp16.h>
#include <cstdint>

// Problem constants (fixed by the reference setup)
#define HH 240
#define WW 304
#define IN_CH 16
#define OUT_CH 32
#define CIN 18            // pos + neg + 16 features
#define CPAD 20           // dense per-pixel stride: [pos,neg,f0..f15,cnt,pad]
#define BB 8
#define NPIX (BB * HH * WW)          // 583680
#define NMAX (BB * 65536)            // 524288 events
#define WSIZE (3 * 3 * CIN * OUT_CH) // 5184 weights

// Conv tiling (fp16 tensor cores, legacy mma path)
#define TLX 32            // output tile width
#define TLY 8             // output tile height
#define HLX (TLX + 2)     // 34 staged cols
#define HLY (TLY + 2)     // 10 staged rows
#define STPX (HLX * HLY)  // 340 staged pixels
#define APITCH 40         // halves per staged pixel (32 data + 8 pad = 80B row)
#define BPITCH 36         // halves per weight n-row (32 data + 4 pad)

// Scratch (device globals: no allocation allowed in kernel_launch)
__device__ float g_dense[(size_t)NPIX * CPAD];   // ~46.7 MB accumulator (+count)
__device__ float g_conv [(size_t)NPIX * OUT_CH]; // ~74.7 MB conv output
__device__ int   g_key  [NMAX];

__device__ __forceinline__ uint32_t smem_u32(const void* p) {
    uint32_t a;
    asm("{ .reg .u64 t; cvta.to.shared.u64 t, %1; cvt.u32.u64 %0, t; }"
        : "=r"(a) : "l"(p));
    return a;
}

// ---------------------------------------------------------------------------
// 0) Zero the accumulator (must happen every graph replay)
// ---------------------------------------------------------------------------
__global__ void zero_dense_kernel() {
    const size_t n4 = (size_t)NPIX * CPAD / 4;
    size_t i = (size_t)blockIdx.x * blockDim.x + threadIdx.x;
    float4* p = reinterpret_cast<float4*>(g_dense);
    if (i < n4) p[i] = make_float4(0.f, 0.f, 0.f, 0.f);
}

// ---------------------------------------------------------------------------
// 1) Scatter: per-event float4 atomics into the dense grid; cache key.
//    offsets may be int32 or int64 (values positive < 2^31, so for
//    little-endian int64 the second 32-bit word is 0).
// ---------------------------------------------------------------------------
__global__ void scatter_kernel(const float* __restrict__ events,
                               const float* __restrict__ features,
                               const int* __restrict__ offsets_raw,
                               int n, int nb) {
    int i = blockIdx.x * blockDim.x + threadIdx.x;
    if (i >= n) return;

    bool is64 = (nb > 1) ? (__ldg(&offsets_raw[1]) == 0) : false;

    float4 ev = *reinterpret_cast<const float4*>(events + (size_t)i * 4);

    int b = 0;
    #pragma unroll
    for (int j = 0; j < BB; j++) {
        if (j < nb) {
            long long oj = is64
                ? __ldg(reinterpret_cast<const long long*>(offsets_raw) + j)
                : (long long)__ldg(&offsets_raw[j]);
            if (oj <= (long long)i) b++;
        }
    }

    int yi = __float2int_rn(ev.y * (float)HH);
    int xi = __float2int_rn(ev.x * (float)WW);
    yi = min(max(yi, 0), HH - 1);
    xi = min(max(xi, 0), WW - 1);
    int key = (b * HH + yi) * WW + xi;
    g_key[i] = key;

    float pos = ev.w;
    float neg = 1.0f - pos;

    const float4* f = reinterpret_cast<const float4*>(features + (size_t)i * IN_CH);
    float4 f0 = f[0], f1 = f[1], f2 = f[2], f3 = f[3];

    float* d = g_dense + (size_t)key * CPAD;
    atomicAdd(reinterpret_cast<float4*>(d +  0), make_float4(pos,  neg,  f0.x, f0.y));
    atomicAdd(reinterpret_cast<float4*>(d +  4), make_float4(f0.z, f0.w, f1.x, f1.y));
    atomicAdd(reinterpret_cast<float4*>(d +  8), make_float4(f1.z, f1.w, f2.x, f2.y));
    atomicAdd(reinterpret_cast<float4*>(d + 12), make_float4(f2.z, f2.w, f3.x, f3.y));
    atomicAdd(reinterpret_cast<float4*>(d + 16), make_float4(f3.z, f3.w, 1.0f, 0.0f));
}

// ---------------------------------------------------------------------------
// 2) Conv 3x3 SAME via fp16 mma.m16n8k16 (fp32 accum), ldmatrix A fragments.
//    Block: 512 thr = 16 warps; output tile 32x8 px; warp: 16 px x 32 oc.
//    A: halo 34x10 px staged fp16, normalized, K padded 18->32, pitch 80B
//       (conflict-free ldmatrix). B: [tap][n][k] fp16, n-pitch 36 halves
//       (conflict-free 32-bit loads). 9 taps x 2 ksteps x 4 ntiles mma.
// ---------------------------------------------------------------------------
__global__ __launch_bounds__(512) void conv_hmma_kernel(const float* __restrict__ weight) {
    __shared__ __half sA[STPX * APITCH];          // 27200 B
    __shared__ __half sB[9 * OUT_CH * BPITCH];    // 20736 B  (total 47936 B)

    const int tid = threadIdx.x;
    const int b  = blockIdx.z;
    const int y0 = blockIdx.y * TLY;
    const int x0 = blockIdx.x * TLX;

    // ---- stage B: sB[tap][n][k] = half(W[tap][k][n]), k>=18 zero ----
    for (int i = tid; i < 9 * OUT_CH * 32; i += 512) {
        int tap = i >> 10;          // 32n * 32k = 1024 per tap
        int r   = i & 1023;
        int nn  = r >> 5;
        int k   = r & 31;
        float v = (k < CIN) ? __ldg(&weight[(tap * CIN + k) * OUT_CH + nn]) : 0.f;
        sB[(tap * OUT_CH + nn) * BPITCH + k] = __float2half_rn(v);
    }

    // ---- stage A: normalized dense pixels as fp16, zeros outside image ----
    for (int s = tid; s < STPX; s += 512) {
        int hy = s / HLX;
        int hx = s - hy * HLX;
        int gy = y0 + hy - 1;
        int gx = x0 + hx - 1;
        float v[CIN];
        #pragma unroll
        for (int c = 0; c < CIN; c++) v[c] = 0.f;
        if ((unsigned)gy < (unsigned)HH && (unsigned)gx < (unsigned)WW) {
            const float* d = g_dense + ((size_t)(b * HH + gy) * WW + gx) * CPAD;
            float4 a0 = *reinterpret_cast<const float4*>(d + 0);
            float4 a1 = *reinterpret_cast<const float4*>(d + 4);
            float4 a2 = *reinterpret_cast<const float4*>(d + 8);
            float4 a3 = *reinterpret_cast<const float4*>(d + 12);
            float4 a4 = *reinterpret_cast<const float4*>(d + 16); // f14,f15,cnt,-
            float inv = 1.0f / fmaxf(a4.z, 1.0f);
            v[0]=a0.x*inv;  v[1]=a0.y*inv;  v[2]=a0.z*inv;  v[3]=a0.w*inv;
            v[4]=a1.x*inv;  v[5]=a1.y*inv;  v[6]=a1.z*inv;  v[7]=a1.w*inv;
            v[8]=a2.x*inv;  v[9]=a2.y*inv;  v[10]=a2.z*inv; v[11]=a2.w*inv;
            v[12]=a3.x*inv; v[13]=a3.y*inv; v[14]=a3.z*inv; v[15]=a3.w*inv;
            v[16]=a4.x*inv; v[17]=a4.y*inv;
        }
        // pack 40 halves (32 data + 8 pad) = 5 x uint4
        uint32_t w[20];
        #pragma unroll
        for (int j = 0; j < 9; j++) {
            __half2 h = __floats2half2_rn(v[2*j], v[2*j+1]);
            w[j] = *reinterpret_cast<uint32_t*>(&h);
        }
        #pragma unroll
        for (int j = 9; j < 20; j++) w[j] = 0u;
        uint4* dst = reinterpret_cast<uint4*>(sA + (size_t)s * APITCH);
        #pragma unroll
        for (int q = 0; q < 5; q++)
            dst[q] = make_uint4(w[q*4+0], w[q*4+1], w[q*4+2], w[q*4+3]);
    }
    __syncthreads();

    // ---- main loop ----
    const int warp = tid >> 5;
    const int lane = tid & 31;
    const int gid  = lane >> 2;   // 0..7
    const int t4   = lane & 3;    // 0..3
    const int ty   = warp >> 1;          // 0..7
    const int tx   = (warp & 1) * 16;    // 0 or 16

    const uint32_t sA_addr = smem_u32(sA);
    // ldmatrix lane->address: row = lane&15, col-half = lane>>4
    const uint32_t lm_off = (uint32_t)(lane & 15) * (APITCH * 2)
                          + (uint32_t)(lane >> 4) * 16;

    float acc[4][4];
    #pragma unroll
    for (int nt = 0; nt < 4; nt++)
        #pragma unroll
        for (int r = 0; r < 4; r++) acc[nt][r] = 0.f;

    #pragma unroll
    for (int tap = 0; tap < 9; tap++) {
        const int ky = tap / 3;
        const int kx = tap - ky * 3;
        const uint32_t px0 = (uint32_t)((ty + ky) * HLX + tx + kx);
        const uint32_t abase = sA_addr + px0 * (APITCH * 2) + lm_off;
        #pragma unroll
        for (int ks = 0; ks < 2; ks++) {
            uint32_t a0, a1, a2, a3;
            asm volatile(
                "ldmatrix.sync.aligned.m8n8.x4.shared.b16 {%0,%1,%2,%3}, [%4];"
                : "=r"(a0), "=r"(a1), "=r"(a2), "=r"(a3)
                : "r"(abase + ks * 32));
            #pragma unroll
            for (int nt = 0; nt < 4; nt++) {
                const __half* bp = sB + (size_t)(tap * OUT_CH + nt * 8 + gid) * BPITCH
                                 + ks * 16 + t4 * 2;
                uint32_t b0 = *reinterpret_cast<const uint32_t*>(bp);
                uint32_t b1 = *reinterpret_cast<const uint32_t*>(bp + 8);
                asm volatile(
                    "mma.sync.aligned.m16n8k16.row.col.f32.f16.f16.f32 "
                    "{%0,%1,%2,%3}, {%4,%5,%6,%7}, {%8,%9}, {%0,%1,%2,%3};"
                    : "+f"(acc[nt][0]), "+f"(acc[nt][1]),
                      "+f"(acc[nt][2]), "+f"(acc[nt][3])
                    : "r"(a0), "r"(a1), "r"(a2), "r"(a3), "r"(b0), "r"(b1));
            }
        }
    }

    // ---- epilogue: D rows = pixels (gid, gid+8), cols = out channels ----
    const int gy  = y0 + ty;
    const int gx1 = x0 + tx + gid;
    const int gx2 = gx1 + 8;
    #pragma unroll
    for (int nt = 0; nt < 4; nt++) {
        int col = nt * 8 + t4 * 2;
        if (gx1 < WW)
            *reinterpret_cast<float2*>(
                g_conv + ((size_t)(b * HH + gy) * WW + gx1) * OUT_CH + col) =
                make_float2(acc[nt][0], acc[nt][1]);
        if (gx2 < WW)
            *reinterpret_cast<float2*>(
                g_conv + ((size_t)(b * HH + gy) * WW + gx2) * OUT_CH + col) =
                make_float2(acc[nt][2], acc[nt][3]);
    }
}

// ---------------------------------------------------------------------------
// 3) Gather: f[i] = conv[key[i]] + bias   (8 threads / event, float4 each)
// ---------------------------------------------------------------------------
__global__ void gather_kernel(const float* __restrict__ bias,
                              float* __restrict__ out, int n) {
    int t = blockIdx.x * blockDim.x + threadIdx.x;
    if (t >= n * 8) return;
    int e = t >> 3;
    int q = t & 7;
    int key = g_key[e];
    float4 v = *reinterpret_cast<const float4*>(g_conv + (size_t)key * OUT_CH + q * 4);
    float4 bb = *reinterpret_cast<const float4*>(bias + q * 4);
    v.x += bb.x; v.y += bb.y; v.z += bb.z; v.w += bb.w;
    *reinterpret_cast<float4*>(out + (size_t)e * OUT_CH + q * 4) = v;
}

// ---------------------------------------------------------------------------
extern "C" void kernel_launch(void* const* d_in, const int* in_sizes, int n_in,
                              void* d_out, int out_size) {
    // Identify inputs by element count (robust to ordering):
    //   events: N*4, features: N*16, weight: 5184, bias: 32, offsets: 8
    const float* events   = nullptr;
    const float* features = nullptr;
    const float* weight   = nullptr;
    const float* bias     = nullptr;
    const int*   offsets  = nullptr;
    int n = 0, nb = 0;

    int big0 = -1, big1 = -1;
    for (int i = 0; i < n_in; i++) {
        int s = in_sizes[i];
        if (s == WSIZE)            weight  = (const float*)d_in[i];
        else if (s == OUT_CH)      bias    = (const float*)d_in[i];
        else if (s <= 64)        { offsets = (const int*)d_in[i]; nb = s; }
        else if (big0 < 0)         big0 = i;
        else                       big1 = i;
    }
    if (in_sizes[big0] > in_sizes[big1]) { int t = big0; big0 = big1; big1 = t; }
    events   = (const float*)d_in[big0];
    features = (const float*)d_in[big1];
    n = in_sizes[big0] / 4;
    if (nb > BB) nb = BB;

    const int T = 256;

    // 0) zero accumulator
    {
        size_t n4 = (size_t)NPIX * CPAD / 4;
        int blocks = (int)((n4 + T - 1) / T);
        zero_dense_kernel<<<blocks, T>>>();
    }
    // 1) scatter
    scatter_kernel<<<(n + T - 1) / T, T>>>(events, features, offsets, n, nb);
    // 2) conv on fp16 tensor cores (normalization fused into halo staging)
    {
        dim3 grid((WW + TLX - 1) / TLX, HH / TLY, BB);   // 10 x 30 x 8
        conv_hmma_kernel<<<grid, 512>>>(weight);
    }
    // 3) gather + bias
    gather_kernel<<<(n * 8 + T - 1) / T, T>>>(bias, (float*)d_out, n);
}

// round 13
// speedup vs baseline: 1.6643x; 1.0064x over previous
#include <cuda_runtime.h>
#include <cuda_fp16.h>
#include <cstdint>

// Problem constants (fixed by the reference setup)
#define HH 240
#define WW 304
#define IN_CH 16
#define OUT_CH 32
#define CIN 18            // pos + neg + 16 features
#define CPAD 20           // dense per-pixel stride: [pos,neg,f0..f15,cnt,pad]
#define BB 8
#define NPIX (BB * HH * WW)          // 583680
#define NMAX (BB * 65536)            // 524288 events
#define WSIZE (3 * 3 * CIN * OUT_CH) // 5184 weights

// Conv tiling (fp16 tensor cores, legacy mma path)
#define TLX 32            // output tile width
#define TLY 8             // output tile height
#define HLX (TLX + 2)     // 34 staged cols
#define HLY (TLY + 2)     // 10 staged rows
#define STPX (HLX * HLY)  // 340 staged pixels
#define APITCH 40         // halves per staged pixel (32 data + 8 pad = 80B row)
#define BPITCH 36         // halves per weight n-row (32 data + 4 pad)

// Scratch (device globals: no allocation allowed in kernel_launch)
__device__ float g_dense[(size_t)NPIX * CPAD];   // ~46.7 MB accumulator (+count)
__device__ float g_conv [(size_t)NPIX * OUT_CH]; // ~74.7 MB conv output
__device__ int   g_key  [NMAX];

__device__ __forceinline__ uint32_t smem_u32(const void* p) {
    uint32_t a;
    asm("{ .reg .u64 t; cvta.to.shared.u64 t, %1; cvt.u32.u64 %0, t; }"
        : "=r"(a) : "l"(p));
    return a;
}

// ---------------------------------------------------------------------------
// 0) Zero the accumulator (must happen every graph replay)
// ---------------------------------------------------------------------------
__global__ void zero_dense_kernel() {
    const size_t n4 = (size_t)NPIX * CPAD / 4;
    size_t i = (size_t)blockIdx.x * blockDim.x + threadIdx.x;
    float4* p = reinterpret_cast<float4*>(g_dense);
    if (i < n4) p[i] = make_float4(0.f, 0.f, 0.f, 0.f);
}

// ---------------------------------------------------------------------------
// 1) Scatter: per-event float4 atomics into the dense grid; cache key.
//    offsets may be int32 or int64 (values positive < 2^31, so for
//    little-endian int64 the second 32-bit word is 0).
// ---------------------------------------------------------------------------
__global__ void scatter_kernel(const float* __restrict__ events,
                               const float* __restrict__ features,
                               const int* __restrict__ offsets_raw,
                               int n, int nb) {
    int i = blockIdx.x * blockDim.x + threadIdx.x;
    if (i >= n) return;

    bool is64 = (nb > 1) ? (__ldg(&offsets_raw[1]) == 0) : false;

    float4 ev = *reinterpret_cast<const float4*>(events + (size_t)i * 4);

    int b = 0;
    #pragma unroll
    for (int j = 0; j < BB; j++) {
        if (j < nb) {
            long long oj = is64
                ? __ldg(reinterpret_cast<const long long*>(offsets_raw) + j)
                : (long long)__ldg(&offsets_raw[j]);
            if (oj <= (long long)i) b++;
        }
    }

    int yi = __float2int_rn(ev.y * (float)HH);
    int xi = __float2int_rn(ev.x * (float)WW);
    yi = min(max(yi, 0), HH - 1);
    xi = min(max(xi, 0), WW - 1);
    int key = (b * HH + yi) * WW + xi;
    g_key[i] = key;

    float pos = ev.w;
    float neg = 1.0f - pos;

    const float4* f = reinterpret_cast<const float4*>(features + (size_t)i * IN_CH);
    float4 f0 = f[0], f1 = f[1], f2 = f[2], f3 = f[3];

    float* d = g_dense + (size_t)key * CPAD;
    atomicAdd(reinterpret_cast<float4*>(d +  0), make_float4(pos,  neg,  f0.x, f0.y));
    atomicAdd(reinterpret_cast<float4*>(d +  4), make_float4(f0.z, f0.w, f1.x, f1.y));
    atomicAdd(reinterpret_cast<float4*>(d +  8), make_float4(f1.z, f1.w, f2.x, f2.y));
    atomicAdd(reinterpret_cast<float4*>(d + 12), make_float4(f2.z, f2.w, f3.x, f3.y));
    atomicAdd(reinterpret_cast<float4*>(d + 16), make_float4(f3.z, f3.w, 1.0f, 0.0f));
}

// ---------------------------------------------------------------------------
// 2) Conv 3x3 SAME via fp16 mma.m16n8k16 (fp32 accum), ldmatrix A fragments.
//    Block: 512 thr = 16 warps; output tile 32x8 px; warp: 16 px x 32 oc.
//    A: halo 34x10 px staged fp16, normalized, K padded 18->32, pitch 80B
//       (conflict-free ldmatrix). B: [tap][n][k] fp16, n-pitch 36 halves
//       (conflict-free 32-bit loads). 9 taps x 2 ksteps x 4 ntiles mma.
// ---------------------------------------------------------------------------
__global__ __launch_bounds__(512) void conv_hmma_kernel(const float* __restrict__ weight) {
    __shared__ __half sA[STPX * APITCH];          // 27200 B
    __shared__ __half sB[9 * OUT_CH * BPITCH];    // 20736 B  (total 47936 B)

    const int tid = threadIdx.x;
    const int b  = blockIdx.z;
    const int y0 = blockIdx.y * TLY;
    const int x0 = blockIdx.x * TLX;

    // ---- stage B: sB[tap][n][k] = half(W[tap][k][n]), k>=18 zero ----
    for (int i = tid; i < 9 * OUT_CH * 32; i += 512) {
        int tap = i >> 10;          // 32n * 32k = 1024 per tap
        int r   = i & 1023;
        int nn  = r >> 5;
        int k   = r & 31;
        float v = (k < CIN) ? __ldg(&weight[(tap * CIN + k) * OUT_CH + nn]) : 0.f;
        sB[(tap * OUT_CH + nn) * BPITCH + k] = __float2half_rn(v);
    }

    // ---- stage A: normalized dense pixels as fp16, zeros outside image ----
    for (int s = tid; s < STPX; s += 512) {
        int hy = s / HLX;
        int hx = s - hy * HLX;
        int gy = y0 + hy - 1;
        int gx = x0 + hx - 1;
        float v[CIN];
        #pragma unroll
        for (int c = 0; c < CIN; c++) v[c] = 0.f;
        if ((unsigned)gy < (unsigned)HH && (unsigned)gx < (unsigned)WW) {
            const float* d = g_dense + ((size_t)(b * HH + gy) * WW + gx) * CPAD;
            float4 a0 = *reinterpret_cast<const float4*>(d + 0);
            float4 a1 = *reinterpret_cast<const float4*>(d + 4);
            float4 a2 = *reinterpret_cast<const float4*>(d + 8);
            float4 a3 = *reinterpret_cast<const float4*>(d + 12);
            float4 a4 = *reinterpret_cast<const float4*>(d + 16); // f14,f15,cnt,-
            float inv = 1.0f / fmaxf(a4.z, 1.0f);
            v[0]=a0.x*inv;  v[1]=a0.y*inv;  v[2]=a0.z*inv;  v[3]=a0.w*inv;
            v[4]=a1.x*inv;  v[5]=a1.y*inv;  v[6]=a1.z*inv;  v[7]=a1.w*inv;
            v[8]=a2.x*inv;  v[9]=a2.y*inv;  v[10]=a2.z*inv; v[11]=a2.w*inv;
            v[12]=a3.x*inv; v[13]=a3.y*inv; v[14]=a3.z*inv; v[15]=a3.w*inv;
            v[16]=a4.x*inv; v[17]=a4.y*inv;
        }
        // pack 40 halves (32 data + 8 pad) = 5 x uint4
        uint32_t w[20];
        #pragma unroll
        for (int j = 0; j < 9; j++) {
            __half2 h = __floats2half2_rn(v[2*j], v[2*j+1]);
            w[j] = *reinterpret_cast<uint32_t*>(&h);
        }
        #pragma unroll
        for (int j = 9; j < 20; j++) w[j] = 0u;
        uint4* dst = reinterpret_cast<uint4*>(sA + (size_t)s * APITCH);
        #pragma unroll
        for (int q = 0; q < 5; q++)
            dst[q] = make_uint4(w[q*4+0], w[q*4+1], w[q*4+2], w[q*4+3]);
    }
    __syncthreads();

    // ---- main loop ----
    const int warp = tid >> 5;
    const int lane = tid & 31;
    const int gid  = lane >> 2;   // 0..7
    const int t4   = lane & 3;    // 0..3
    const int ty   = warp >> 1;          // 0..7
    const int tx   = (warp & 1) * 16;    // 0 or 16

    const uint32_t sA_addr = smem_u32(sA);
    // ldmatrix lane->address: row = lane&15, col-half = lane>>4
    const uint32_t lm_off = (uint32_t)(lane & 15) * (APITCH * 2)
                          + (uint32_t)(lane >> 4) * 16;

    float acc[4][4];
    #pragma unroll
    for (int nt = 0; nt < 4; nt++)
        #pragma unroll
        for (int r = 0; r < 4; r++) acc[nt][r] = 0.f;

    #pragma unroll
    for (int tap = 0; tap < 9; tap++) {
        const int ky = tap / 3;
        const int kx = tap - ky * 3;
        const uint32_t px0 = (uint32_t)((ty + ky) * HLX + tx + kx);
        const uint32_t abase = sA_addr + px0 * (APITCH * 2) + lm_off;
        #pragma unroll
        for (int ks = 0; ks < 2; ks++) {
            uint32_t a0, a1, a2, a3;
            asm volatile(
                "ldmatrix.sync.aligned.m8n8.x4.shared.b16 {%0,%1,%2,%3}, [%4];"
                : "=r"(a0), "=r"(a1), "=r"(a2), "=r"(a3)
                : "r"(abase + ks * 32));
            #pragma unroll
            for (int nt = 0; nt < 4; nt++) {
                const __half* bp = sB + (size_t)(tap * OUT_CH + nt * 8 + gid) * BPITCH
                                 + ks * 16 + t4 * 2;
                uint32_t b0 = *reinterpret_cast<const uint32_t*>(bp);
                uint32_t b1 = *reinterpret_cast<const uint32_t*>(bp + 8);
                asm volatile(
                    "mma.sync.aligned.m16n8k16.row.col.f32.f16.f16.f32 "
                    "{%0,%1,%2,%3}, {%4,%5,%6,%7}, {%8,%9}, {%0,%1,%2,%3};"
                    : "+f"(acc[nt][0]), "+f"(acc[nt][1]),
                      "+f"(acc[nt][2]), "+f"(acc[nt][3])
                    : "r"(a0), "r"(a1), "r"(a2), "r"(a3), "r"(b0), "r"(b1));
            }
        }
    }

    // ---- epilogue: D rows = pixels (gid, gid+8), cols = out channels ----
    const int gy  = y0 + ty;
    const int gx1 = x0 + tx + gid;
    const int gx2 = gx1 + 8;
    #pragma unroll
    for (int nt = 0; nt < 4; nt++) {
        int col = nt * 8 + t4 * 2;
        if (gx1 < WW)
            *reinterpret_cast<float2*>(
                g_conv + ((size_t)(b * HH + gy) * WW + gx1) * OUT_CH + col) =
                make_float2(acc[nt][0], acc[nt][1]);
        if (gx2 < WW)
            *reinterpret_cast<float2*>(
                g_conv + ((size_t)(b * HH + gy) * WW + gx2) * OUT_CH + col) =
                make_float2(acc[nt][2], acc[nt][3]);
    }
}

// ---------------------------------------------------------------------------
// 3) Gather: f[i] = conv[key[i]] + bias   (8 threads / event, float4 each)
// ---------------------------------------------------------------------------
__global__ void gather_kernel(const float* __restrict__ bias,
                              float* __restrict__ out, int n) {
    int t = blockIdx.x * blockDim.x + threadIdx.x;
    if (t >= n * 8) return;
    int e = t >> 3;
    int q = t & 7;
    int key = g_key[e];
    float4 v = *reinterpret_cast<const float4*>(g_conv + (size_t)key * OUT_CH + q * 4);
    float4 bb = *reinterpret_cast<const float4*>(bias + q * 4);
    v.x += bb.x; v.y += bb.y; v.z += bb.z; v.w += bb.w;
    *reinterpret_cast<float4*>(out + (size_t)e * OUT_CH + q * 4) = v;
}

// ---------------------------------------------------------------------------
extern "C" void kernel_launch(void* const* d_in, const int* in_sizes, int n_in,
                              void* d_out, int out_size) {
    // Identify inputs by element count (robust to ordering):
    //   events: N*4, features: N*16, weight: 5184, bias: 32, offsets: 8
    const float* events   = nullptr;
    const float* features = nullptr;
    const float* weight   = nullptr;
    const float* bias     = nullptr;
    const int*   offsets  = nullptr;
    int n = 0, nb = 0;

    int big0 = -1, big1 = -1;
    for (int i = 0; i < n_in; i++) {
        int s = in_sizes[i];
        if (s == WSIZE)            weight  = (const float*)d_in[i];
        else if (s == OUT_CH)      bias    = (const float*)d_in[i];
        else if (s <= 64)        { offsets = (const int*)d_in[i]; nb = s; }
        else if (big0 < 0)         big0 = i;
        else                       big1 = i;
    }
    if (in_sizes[big0] > in_sizes[big1]) { int t = big0; big0 = big1; big1 = t; }
    events   = (const float*)d_in[big0];
    features = (const float*)d_in[big1];
    n = in_sizes[big0] / 4;
    if (nb > BB) nb = BB;

    const int T = 256;

    // 0) zero accumulator
    {
        size_t n4 = (size_t)NPIX * CPAD / 4;
        int blocks = (int)((n4 + T - 1) / T);
        zero_dense_kernel<<<blocks, T>>>();
    }
    // 1) scatter
    scatter_kernel<<<(n + T - 1) / T, T>>>(events, features, offsets, n, nb);
    // 2) conv on fp16 tensor cores (normalization fused into halo staging)
    {
        dim3 grid((WW + TLX - 1) / TLX, HH / TLY, BB);   // 10 x 30 x 8
        conv_hmma_kernel<<<grid, 512>>>(weight);
    }
    // 3) gather + bias
    gather_kernel<<<(n * 8 + T - 1) / T, T>>>(bias, (float*)d_out, n);
}

// round 14
// speedup vs baseline: 2.4905x; 1.4965x over previous
#include <cuda_runtime.h>
#include <cuda_fp16.h>
#include <cstdint>

// Problem constants (fixed by the reference setup)
#define HH 240
#define WW 304
#define IN_CH 16
#define OUT_CH 32
#define CIN 18            // pos + neg + 16 features
#define CPAD 20           // dense per-pixel stride: [pos,neg,f0..f15,cnt,pad]
#define BB 8
#define NPIX (BB * HH * WW)          // 583680
#define NMAX (BB * 65536)            // 524288 events
#define WSIZE (3 * 3 * CIN * OUT_CH) // 5184 weights

// Conv tiling (fp16 tensor cores, legacy mma path)
#define TLX 32            // output tile width
#define TLY 8             // output tile height
#define HLX (TLX + 2)     // 34 staged cols
#define HLY (TLY + 2)     // 10 staged rows
#define STPX (HLX * HLY)  // 340 staged pixels
#define APITCH 40         // halves per staged pixel (32 data + 8 pad = 80B row)
// B: per tap 12 ldmatrix tiles (8x8 halves = 128B): m0..7 = [nt][kg0,kg1]
// interleaved, m8..11 = [nt][kg2]. Per tap 768 halves = 1536B.
#define BTAP 768

// Scratch (device globals: no allocation allowed in kernel_launch)
__device__ float g_dense[(size_t)NPIX * CPAD];   // ~46.7 MB accumulator (+count)
__device__ float g_conv [(size_t)NPIX * OUT_CH]; // ~74.7 MB conv output
__device__ int   g_key  [NMAX];

__device__ __forceinline__ uint32_t smem_u32(const void* p) {
    uint32_t a;
    asm("{ .reg .u64 t; cvta.to.shared.u64 t, %1; cvt.u32.u64 %0, t; }"
        : "=r"(a) : "l"(p));
    return a;
}

// ---------------------------------------------------------------------------
// 0) Zero the accumulator (must happen every graph replay)
// ---------------------------------------------------------------------------
__global__ void zero_dense_kernel() {
    const size_t n4 = (size_t)NPIX * CPAD / 4;
    size_t i = (size_t)blockIdx.x * blockDim.x + threadIdx.x;
    float4* p = reinterpret_cast<float4*>(g_dense);
    if (i < n4) p[i] = make_float4(0.f, 0.f, 0.f, 0.f);
}

// ---------------------------------------------------------------------------
// 1) Scatter: per-event float4 atomics into the dense grid; cache key.
//    offsets may be int32 or int64 (values positive < 2^31, so for
//    little-endian int64 the second 32-bit word is 0).
// ---------------------------------------------------------------------------
__global__ void scatter_kernel(const float* __restrict__ events,
                               const float* __restrict__ features,
                               const int* __restrict__ offsets_raw,
                               int n, int nb) {
    int i = blockIdx.x * blockDim.x + threadIdx.x;
    if (i >= n) return;

    bool is64 = (nb > 1) ? (__ldg(&offsets_raw[1]) == 0) : false;

    float4 ev = *reinterpret_cast<const float4*>(events + (size_t)i * 4);

    int b = 0;
    #pragma unroll
    for (int j = 0; j < BB; j++) {
        if (j < nb) {
            long long oj = is64
                ? __ldg(reinterpret_cast<const long long*>(offsets_raw) + j)
                : (long long)__ldg(&offsets_raw[j]);
            if (oj <= (long long)i) b++;
        }
    }

    int yi = __float2int_rn(ev.y * (float)HH);
    int xi = __float2int_rn(ev.x * (float)WW);
    yi = min(max(yi, 0), HH - 1);
    xi = min(max(xi, 0), WW - 1);
    int key = (b * HH + yi) * WW + xi;
    g_key[i] = key;

    float pos = ev.w;
    float neg = 1.0f - pos;

    const float4* f = reinterpret_cast<const float4*>(features + (size_t)i * IN_CH);
    float4 f0 = f[0], f1 = f[1], f2 = f[2], f3 = f[3];

    float* d = g_dense + (size_t)key * CPAD;
    atomicAdd(reinterpret_cast<float4*>(d +  0), make_float4(pos,  neg,  f0.x, f0.y));
    atomicAdd(reinterpret_cast<float4*>(d +  4), make_float4(f0.z, f0.w, f1.x, f1.y));
    atomicAdd(reinterpret_cast<float4*>(d +  8), make_float4(f1.z, f1.w, f2.x, f2.y));
    atomicAdd(reinterpret_cast<float4*>(d + 12), make_float4(f2.z, f2.w, f3.x, f3.y));
    atomicAdd(reinterpret_cast<float4*>(d + 16), make_float4(f3.z, f3.w, 1.0f, 0.0f));
}

// ---------------------------------------------------------------------------
// 2) Conv 3x3 SAME via fp16 mma (fp32 accum), all fragments via ldmatrix.
//    Block: 512 thr = 16 warps; output tile 32x8 px; warp: 16 px x 32 oc.
//    Per tap: 1x m16n8k16 + 1x m16n8k8 per n-tile (18 ch -> 16 + 2, no 32-pad
//    waste). A: halo 34x10 px, pitch 80B (conflict-free ldmatrix). B: 8x8
//    ldmatrix tiles, 3x ldmatrix.x4 per tap covers all 4 n-tiles, both ksteps.
//    Epilogue skips stores for pixels with zero events (never gathered).
// ---------------------------------------------------------------------------
__global__ __launch_bounds__(512) void conv_hmma_kernel(const float* __restrict__ weight) {
    __shared__ __half sA[STPX * APITCH];          // 27200 B
    __shared__ __half sB[9 * BTAP];               // 13824 B
    __shared__ float  sCnt[STPX];                 //  1360 B (total 42384 B)

    const int tid = threadIdx.x;
    const int b  = blockIdx.z;
    const int y0 = blockIdx.y * TLY;
    const int x0 = blockIdx.x * TLX;

    // ---- stage B as ldmatrix tiles ----
    // m 0..7: nt = m>>1, kg = m&1 ; m 8..11: nt = m-8, kg = 2
    // element e: n_local = e>>3, kk = e&7 ; value = W[tap][kg*8+kk][nt*8+n_local]
    for (int i = tid; i < 9 * BTAP; i += 512) {
        int tap = i / BTAP;
        int r   = i - tap * BTAP;
        int m   = r >> 6;
        int e   = r & 63;
        int nl  = e >> 3;
        int kk  = e & 7;
        int nt, kg;
        if (m < 8) { nt = m >> 1; kg = m & 1; } else { nt = m - 8; kg = 2; }
        int nn = nt * 8 + nl;
        int k  = kg * 8 + kk;
        float v = (k < CIN) ? __ldg(&weight[(tap * CIN + k) * OUT_CH + nn]) : 0.f;
        sB[i] = __float2half_rn(v);
    }

    // ---- stage A: normalized dense pixels as fp16, zeros outside image ----
    for (int s = tid; s < STPX; s += 512) {
        int hy = s / HLX;
        int hx = s - hy * HLX;
        int gy = y0 + hy - 1;
        int gx = x0 + hx - 1;
        float v[CIN];
        #pragma unroll
        for (int c = 0; c < CIN; c++) v[c] = 0.f;
        float cnt = 0.f;
        if ((unsigned)gy < (unsigned)HH && (unsigned)gx < (unsigned)WW) {
            const float* d = g_dense + ((size_t)(b * HH + gy) * WW + gx) * CPAD;
            float4 a0 = *reinterpret_cast<const float4*>(d + 0);
            float4 a1 = *reinterpret_cast<const float4*>(d + 4);
            float4 a2 = *reinterpret_cast<const float4*>(d + 8);
            float4 a3 = *reinterpret_cast<const float4*>(d + 12);
            float4 a4 = *reinterpret_cast<const float4*>(d + 16); // f14,f15,cnt,-
            cnt = a4.z;
            float inv = 1.0f / fmaxf(cnt, 1.0f);
            v[0]=a0.x*inv;  v[1]=a0.y*inv;  v[2]=a0.z*inv;  v[3]=a0.w*inv;
            v[4]=a1.x*inv;  v[5]=a1.y*inv;  v[6]=a1.z*inv;  v[7]=a1.w*inv;
            v[8]=a2.x*inv;  v[9]=a2.y*inv;  v[10]=a2.z*inv; v[11]=a2.w*inv;
            v[12]=a3.x*inv; v[13]=a3.y*inv; v[14]=a3.z*inv; v[15]=a3.w*inv;
            v[16]=a4.x*inv; v[17]=a4.y*inv;
        }
        sCnt[s] = cnt;
        // pack 40 halves (32 data + 8 pad) = 5 x uint4
        uint32_t w[20];
        #pragma unroll
        for (int j = 0; j < 9; j++) {
            __half2 h = __floats2half2_rn(v[2*j], v[2*j+1]);
            w[j] = *reinterpret_cast<uint32_t*>(&h);
        }
        #pragma unroll
        for (int j = 9; j < 20; j++) w[j] = 0u;
        uint4* dst = reinterpret_cast<uint4*>(sA + (size_t)s * APITCH);
        #pragma unroll
        for (int q = 0; q < 5; q++)
            dst[q] = make_uint4(w[q*4+0], w[q*4+1], w[q*4+2], w[q*4+3]);
    }
    __syncthreads();

    // ---- main loop ----
    const int warp = tid >> 5;
    const int lane = tid & 31;
    const int gid  = lane >> 4;          // (unused for B now)
    const int ty   = warp >> 1;          // 0..7
    const int tx   = (warp & 1) * 16;    // 0 or 16

    const uint32_t sA_addr = smem_u32(sA);
    const uint32_t sB_addr = smem_u32(sB);
    // A x4 (k0-15): lane -> row (lane&15), half (lane>>4)
    const uint32_t lmA_off  = (uint32_t)(lane & 15) * (APITCH * 2)
                            + (uint32_t)(lane >> 4) * 16;
    // A x2 (k16-23): lanes 0-15 -> rows 0-15, +32B k-offset
    const uint32_t lmA2_off = (uint32_t)(lane & 15) * (APITCH * 2) + 32u;
    // B x4: lane -> tile (lane>>3), row (lane&7), rows are 16B apart
    const uint32_t lmB_off  = (uint32_t)(lane >> 3) * 128u
                            + (uint32_t)(lane & 7) * 16u;

    float acc[4][4];
    #pragma unroll
    for (int nt = 0; nt < 4; nt++)
        #pragma unroll
        for (int r = 0; r < 4; r++) acc[nt][r] = 0.f;

    #pragma unroll
    for (int tap = 0; tap < 9; tap++) {
        const int ky = tap / 3;
        const int kx = tap - ky * 3;
        const uint32_t px0 = (uint32_t)((ty + ky) * HLX + tx + kx);
        const uint32_t apx = sA_addr + px0 * (APITCH * 2);

        // A fragments
        uint32_t a0, a1, a2, a3, e0, e1;
        asm volatile(
            "ldmatrix.sync.aligned.m8n8.x4.shared.b16 {%0,%1,%2,%3}, [%4];"
            : "=r"(a0), "=r"(a1), "=r"(a2), "=r"(a3)
            : "r"(apx + lmA_off));
        asm volatile(
            "ldmatrix.sync.aligned.m8n8.x2.shared.b16 {%0,%1}, [%2];"
            : "=r"(e0), "=r"(e1)
            : "r"(apx + lmA2_off));

        // B fragments: 3 x4 groups
        const uint32_t bbase = sB_addr + (uint32_t)tap * (BTAP * 2) + lmB_off;
        uint32_t b00, b01, b10, b11;   // nt0:{k16}, nt1:{k16}
        uint32_t b20, b21, b30, b31;   // nt2, nt3
        uint32_t c0, c1, c2, c3;       // k8-step for nt0..3
        asm volatile(
            "ldmatrix.sync.aligned.m8n8.x4.shared.b16 {%0,%1,%2,%3}, [%4];"
            : "=r"(b00), "=r"(b01), "=r"(b10), "=r"(b11) : "r"(bbase));
        asm volatile(
            "ldmatrix.sync.aligned.m8n8.x4.shared.b16 {%0,%1,%2,%3}, [%4];"
            : "=r"(b20), "=r"(b21), "=r"(b30), "=r"(b31) : "r"(bbase + 512u));
        asm volatile(
            "ldmatrix.sync.aligned.m8n8.x4.shared.b16 {%0,%1,%2,%3}, [%4];"
            : "=r"(c0), "=r"(c1), "=r"(c2), "=r"(c3) : "r"(bbase + 1024u));

        #define MMA16(NT, B0, B1)                                             \
            asm volatile(                                                      \
                "mma.sync.aligned.m16n8k16.row.col.f32.f16.f16.f32 "           \
                "{%0,%1,%2,%3}, {%4,%5,%6,%7}, {%8,%9}, {%0,%1,%2,%3};"        \
                : "+f"(acc[NT][0]), "+f"(acc[NT][1]),                          \
                  "+f"(acc[NT][2]), "+f"(acc[NT][3])                           \
                : "r"(a0), "r"(a1), "r"(a2), "r"(a3), "r"(B0), "r"(B1))
        #define MMA8(NT, B0)                                                   \
            asm volatile(                                                      \
                "mma.sync.aligned.m16n8k8.row.col.f32.f16.f16.f32 "            \
                "{%0,%1,%2,%3}, {%4,%5}, {%6}, {%0,%1,%2,%3};"                 \
                : "+f"(acc[NT][0]), "+f"(acc[NT][1]),                          \
                  "+f"(acc[NT][2]), "+f"(acc[NT][3])                           \
                : "r"(e0), "r"(e1), "r"(B0))

        MMA16(0, b00, b01); MMA16(1, b10, b11);
        MMA16(2, b20, b21); MMA16(3, b30, b31);
        MMA8(0, c0); MMA8(1, c1); MMA8(2, c2); MMA8(3, c3);
        #undef MMA16
        #undef MMA8
    }

    // ---- epilogue: D rows = pixels (g, g+8), cols = out channels.
    //      Skip stores for pixels with no events (never gathered). ----
    const int g    = lane >> 2;   // 0..7
    const int t4   = lane & 3;    // 0..3
    const int gy   = y0 + ty;
    const int gx1  = x0 + tx + g;
    const int gx2  = gx1 + 8;
    const int sp1  = (ty + 1) * HLX + (tx + g + 1);
    const bool w1  = (gx1 < WW) && (sCnt[sp1] > 0.f);
    const bool w2  = (gx2 < WW) && (sCnt[sp1 + 8] > 0.f);
    #pragma unroll
    for (int nt = 0; nt < 4; nt++) {
        int col = nt * 8 + t4 * 2;
        if (w1)
            *reinterpret_cast<float2*>(
                g_conv + ((size_t)(b * HH + gy) * WW + gx1) * OUT_CH + col) =
                make_float2(acc[nt][0], acc[nt][1]);
        if (w2)
            *reinterpret_cast<float2*>(
                g_conv + ((size_t)(b * HH + gy) * WW + gx2) * OUT_CH + col) =
                make_float2(acc[nt][2], acc[nt][3]);
    }
}

// ---------------------------------------------------------------------------
// 3) Gather: f[i] = conv[key[i]] + bias   (8 threads / event, float4 each)
// ---------------------------------------------------------------------------
__global__ void gather_kernel(const float* __restrict__ bias,
                              float* __restrict__ out, int n) {
    int t = blockIdx.x * blockDim.x + threadIdx.x;
    if (t >= n * 8) return;
    int e = t >> 3;
    int q = t & 7;
    int key = g_key[e];
    float4 v = *reinterpret_cast<const float4*>(g_conv + (size_t)key * OUT_CH + q * 4);
    float4 bb = *reinterpret_cast<const float4*>(bias + q * 4);
    v.x += bb.x; v.y += bb.y; v.z += bb.z; v.w += bb.w;
    *reinterpret_cast<float4*>(out + (size_t)e * OUT_CH + q * 4) = v;
}

// ---------------------------------------------------------------------------
extern "C" void kernel_launch(void* const* d_in, const int* in_sizes, int n_in,
                              void* d_out, int out_size) {
    // Identify inputs by element count (robust to ordering):
    //   events: N*4, features: N*16, weight: 5184, bias: 32, offsets: 8
    const float* events   = nullptr;
    const float* features = nullptr;
    const float* weight   = nullptr;
    const float* bias     = nullptr;
    const int*   offsets  = nullptr;
    int n = 0, nb = 0;

    int big0 = -1, big1 = -1;
    for (int i = 0; i < n_in; i++) {
        int s = in_sizes[i];
        if (s == WSIZE)            weight  = (const float*)d_in[i];
        else if (s == OUT_CH)      bias    = (const float*)d_in[i];
        else if (s <= 64)        { offsets = (const int*)d_in[i]; nb = s; }
        else if (big0 < 0)         big0 = i;
        else                       big1 = i;
    }
    if (in_sizes[big0] > in_sizes[big1]) { int t = big0; big0 = big1; big1 = t; }
    events   = (const float*)d_in[big0];
    features = (const float*)d_in[big1];
    n = in_sizes[big0] / 4;
    if (nb > BB) nb = BB;

    const int T = 256;

    // 0) zero accumulator
    {
        size_t n4 = (size_t)NPIX * CPAD / 4;
        int blocks = (int)((n4 + T - 1) / T);
        zero_dense_kernel<<<blocks, T>>>();
    }
    // 1) scatter
    scatter_kernel<<<(n + T - 1) / T, T>>>(events, features, offsets, n, nb);
    // 2) conv on fp16 tensor cores (normalization fused into halo staging)
    {
        dim3 grid((WW + TLX - 1) / TLX, HH / TLY, BB);   // 10 x 30 x 8
        conv_hmma_kernel<<<grid, 512>>>(weight);
    }
    // 3) gather + bias
    gather_kernel<<<(n * 8 + T - 1) / T, T>>>(bias, (float*)d_out, n);
}

// round 15
// speedup vs baseline: 2.7282x; 1.0955x over previous
#include <cuda_runtime.h>
#include <cuda_fp16.h>
#include <cstdint>

// Problem constants (fixed by the reference setup)
#define HH 240
#define WW 304
#define IN_CH 16
#define OUT_CH 32
#define CIN 18            // pos + neg + 16 features
#define CPAD 20           // dense per-pixel stride: [pos,neg,f0..f15,cnt,pad]
#define BB 8
#define NPIX (BB * HH * WW)          // 583680
#define NMAX (BB * 65536)            // 524288 events
#define WSIZE (3 * 3 * CIN * OUT_CH) // 5184 weights

// Conv tiling (fp16 tensor cores, legacy mma path)
#define TLX 32            // output tile width
#define TLY 16            // output tile height
#define HLX (TLX + 2)     // 34 staged cols
#define HLY (TLY + 2)     // 18 staged rows
#define STPX (HLX * HLY)  // 612 staged pixels
#define APITCH 40         // halves per staged pixel (32 data + 8 pad = 80B row)
#define BTAP 768          // halves per tap of B ldmatrix tiles (12 x 8x8)
#define CONV_THREADS 1024

// Dynamic smem layout (bytes)
#define SA_BYTES (STPX * APITCH * 2)        // 48960
#define SB_BYTES (9 * BTAP * 2)             // 13824
#define SC_BYTES (STPX * 4)                 //  2448
#define DYN_BYTES (SA_BYTES + SB_BYTES + SC_BYTES)  // 65232

// Scratch (device globals: no allocation allowed in kernel_launch)
__device__ float g_dense[(size_t)NPIX * CPAD];   // ~46.7 MB accumulator (+count)
__device__ float g_conv [(size_t)NPIX * OUT_CH]; // ~74.7 MB conv output
__device__ int   g_key  [NMAX];

__device__ __forceinline__ uint32_t smem_u32(const void* p) {
    uint32_t a;
    asm("{ .reg .u64 t; cvta.to.shared.u64 t, %1; cvt.u32.u64 %0, t; }"
        : "=r"(a) : "l"(p));
    return a;
}

// ---------------------------------------------------------------------------
// 0) Zero the accumulator (must happen every graph replay)
// ---------------------------------------------------------------------------
__global__ void zero_dense_kernel() {
    const size_t n4 = (size_t)NPIX * CPAD / 4;
    size_t i = (size_t)blockIdx.x * blockDim.x + threadIdx.x;
    float4* p = reinterpret_cast<float4*>(g_dense);
    if (i < n4) p[i] = make_float4(0.f, 0.f, 0.f, 0.f);
}

// ---------------------------------------------------------------------------
// 1) Scatter: per-event float4 atomics into the dense grid; cache key.
//    offsets may be int32 or int64 (values positive < 2^31, so for
//    little-endian int64 the second 32-bit word is 0).
// ---------------------------------------------------------------------------
__global__ void scatter_kernel(const float* __restrict__ events,
                               const float* __restrict__ features,
                               const int* __restrict__ offsets_raw,
                               int n, int nb) {
    int i = blockIdx.x * blockDim.x + threadIdx.x;
    if (i >= n) return;

    bool is64 = (nb > 1) ? (__ldg(&offsets_raw[1]) == 0) : false;

    float4 ev = *reinterpret_cast<const float4*>(events + (size_t)i * 4);

    int b = 0;
    #pragma unroll
    for (int j = 0; j < BB; j++) {
        if (j < nb) {
            long long oj = is64
                ? __ldg(reinterpret_cast<const long long*>(offsets_raw) + j)
                : (long long)__ldg(&offsets_raw[j]);
            if (oj <= (long long)i) b++;
        }
    }

    int yi = __float2int_rn(ev.y * (float)HH);
    int xi = __float2int_rn(ev.x * (float)WW);
    yi = min(max(yi, 0), HH - 1);
    xi = min(max(xi, 0), WW - 1);
    int key = (b * HH + yi) * WW + xi;
    g_key[i] = key;

    float pos = ev.w;
    float neg = 1.0f - pos;

    const float4* f = reinterpret_cast<const float4*>(features + (size_t)i * IN_CH);
    float4 f0 = f[0], f1 = f[1], f2 = f[2], f3 = f[3];

    float* d = g_dense + (size_t)key * CPAD;
    atomicAdd(reinterpret_cast<float4*>(d +  0), make_float4(pos,  neg,  f0.x, f0.y));
    atomicAdd(reinterpret_cast<float4*>(d +  4), make_float4(f0.z, f0.w, f1.x, f1.y));
    atomicAdd(reinterpret_cast<float4*>(d +  8), make_float4(f1.z, f1.w, f2.x, f2.y));
    atomicAdd(reinterpret_cast<float4*>(d + 12), make_float4(f2.z, f2.w, f3.x, f3.y));
    atomicAdd(reinterpret_cast<float4*>(d + 16), make_float4(f3.z, f3.w, 1.0f, 0.0f));
}

// ---------------------------------------------------------------------------
// 2) Conv 3x3 SAME via fp16 mma (fp32 accum), all fragments via ldmatrix.
//    Block: 1024 thr = 32 warps; output tile 32x16 px; warp: 16 px x 32 oc.
//    Per tap: 1x m16n8k16 + 1x m16n8k8 per n-tile (18 ch -> 16 + 2).
//    A: halo 34x18 px, pitch 80B (conflict-free ldmatrix). B: 8x8 ldmatrix
//    tiles, 3x ldmatrix.x4 per tap. Epilogue skips stores for empty pixels.
// ---------------------------------------------------------------------------
extern __shared__ char dynsmem[];

__global__ __launch_bounds__(CONV_THREADS) void conv_hmma_kernel(const float* __restrict__ weight) {
    __half* sA   = reinterpret_cast<__half*>(dynsmem);
    __half* sB   = reinterpret_cast<__half*>(dynsmem + SA_BYTES);
    float*  sCnt = reinterpret_cast<float*>(dynsmem + SA_BYTES + SB_BYTES);

    const int tid = threadIdx.x;
    const int b  = blockIdx.z;
    const int y0 = blockIdx.y * TLY;
    const int x0 = blockIdx.x * TLX;

    // ---- stage B as ldmatrix tiles ----
    // m 0..7: nt = m>>1, kg = m&1 ; m 8..11: nt = m-8, kg = 2
    // element e: n_local = e>>3, kk = e&7 ; value = W[tap][kg*8+kk][nt*8+n_local]
    for (int i = tid; i < 9 * BTAP; i += CONV_THREADS) {
        int tap = i / BTAP;
        int r   = i - tap * BTAP;
        int m   = r >> 6;
        int e   = r & 63;
        int nl  = e >> 3;
        int kk  = e & 7;
        int nt, kg;
        if (m < 8) { nt = m >> 1; kg = m & 1; } else { nt = m - 8; kg = 2; }
        int nn = nt * 8 + nl;
        int k  = kg * 8 + kk;
        float v = (k < CIN) ? __ldg(&weight[(tap * CIN + k) * OUT_CH + nn]) : 0.f;
        sB[i] = __float2half_rn(v);
    }

    // ---- stage A: normalized dense pixels as fp16, zeros outside image ----
    for (int s = tid; s < STPX; s += CONV_THREADS) {
        int hy = s / HLX;
        int hx = s - hy * HLX;
        int gy = y0 + hy - 1;
        int gx = x0 + hx - 1;
        float v[CIN];
        #pragma unroll
        for (int c = 0; c < CIN; c++) v[c] = 0.f;
        float cnt = 0.f;
        if ((unsigned)gy < (unsigned)HH && (unsigned)gx < (unsigned)WW) {
            const float* d = g_dense + ((size_t)(b * HH + gy) * WW + gx) * CPAD;
            float4 a0 = *reinterpret_cast<const float4*>(d + 0);
            float4 a1 = *reinterpret_cast<const float4*>(d + 4);
            float4 a2 = *reinterpret_cast<const float4*>(d + 8);
            float4 a3 = *reinterpret_cast<const float4*>(d + 12);
            float4 a4 = *reinterpret_cast<const float4*>(d + 16); // f14,f15,cnt,-
            cnt = a4.z;
            float inv = 1.0f / fmaxf(cnt, 1.0f);
            v[0]=a0.x*inv;  v[1]=a0.y*inv;  v[2]=a0.z*inv;  v[3]=a0.w*inv;
            v[4]=a1.x*inv;  v[5]=a1.y*inv;  v[6]=a1.z*inv;  v[7]=a1.w*inv;
            v[8]=a2.x*inv;  v[9]=a2.y*inv;  v[10]=a2.z*inv; v[11]=a2.w*inv;
            v[12]=a3.x*inv; v[13]=a3.y*inv; v[14]=a3.z*inv; v[15]=a3.w*inv;
            v[16]=a4.x*inv; v[17]=a4.y*inv;
        }
        sCnt[s] = cnt;
        // pack 40 halves (32 data + 8 pad) = 5 x uint4
        uint32_t w[20];
        #pragma unroll
        for (int j = 0; j < 9; j++) {
            __half2 h = __floats2half2_rn(v[2*j], v[2*j+1]);
            w[j] = *reinterpret_cast<uint32_t*>(&h);
        }
        #pragma unroll
        for (int j = 9; j < 20; j++) w[j] = 0u;
        uint4* dst = reinterpret_cast<uint4*>(sA + (size_t)s * APITCH);
        #pragma unroll
        for (int q = 0; q < 5; q++)
            dst[q] = make_uint4(w[q*4+0], w[q*4+1], w[q*4+2], w[q*4+3]);
    }
    __syncthreads();

    // ---- main loop ----
    const int warp = tid >> 5;
    const int lane = tid & 31;
    const int ty   = warp >> 1;          // 0..15
    const int tx   = (warp & 1) * 16;    // 0 or 16

    const uint32_t sA_addr = smem_u32(sA);
    const uint32_t sB_addr = smem_u32(sB);
    // A x4 (k0-15): lane -> row (lane&15), half (lane>>4)
    const uint32_t lmA_off  = (uint32_t)(lane & 15) * (APITCH * 2)
                            + (uint32_t)(lane >> 4) * 16;
    // A x2 (k16-23): lanes 0-15 -> rows 0-15, +32B k-offset
    const uint32_t lmA2_off = (uint32_t)(lane & 15) * (APITCH * 2) + 32u;
    // B x4: lane -> tile (lane>>3), row (lane&7), rows are 16B apart
    const uint32_t lmB_off  = (uint32_t)(lane >> 3) * 128u
                            + (uint32_t)(lane & 7) * 16u;

    float acc[4][4];
    #pragma unroll
    for (int nt = 0; nt < 4; nt++)
        #pragma unroll
        for (int r = 0; r < 4; r++) acc[nt][r] = 0.f;

    #pragma unroll
    for (int tap = 0; tap < 9; tap++) {
        const int ky = tap / 3;
        const int kx = tap - ky * 3;
        const uint32_t px0 = (uint32_t)((ty + ky) * HLX + tx + kx);
        const uint32_t apx = sA_addr + px0 * (APITCH * 2);

        // A fragments
        uint32_t a0, a1, a2, a3, e0, e1;
        asm volatile(
            "ldmatrix.sync.aligned.m8n8.x4.shared.b16 {%0,%1,%2,%3}, [%4];"
            : "=r"(a0), "=r"(a1), "=r"(a2), "=r"(a3)
            : "r"(apx + lmA_off));
        asm volatile(
            "ldmatrix.sync.aligned.m8n8.x2.shared.b16 {%0,%1}, [%2];"
            : "=r"(e0), "=r"(e1)
            : "r"(apx + lmA2_off));

        // B fragments: 3 x4 groups
        const uint32_t bbase = sB_addr + (uint32_t)tap * (BTAP * 2) + lmB_off;
        uint32_t b00, b01, b10, b11;
        uint32_t b20, b21, b30, b31;
        uint32_t c0, c1, c2, c3;
        asm volatile(
            "ldmatrix.sync.aligned.m8n8.x4.shared.b16 {%0,%1,%2,%3}, [%4];"
            : "=r"(b00), "=r"(b01), "=r"(b10), "=r"(b11) : "r"(bbase));
        asm volatile(
            "ldmatrix.sync.aligned.m8n8.x4.shared.b16 {%0,%1,%2,%3}, [%4];"
            : "=r"(b20), "=r"(b21), "=r"(b30), "=r"(b31) : "r"(bbase + 512u));
        asm volatile(
            "ldmatrix.sync.aligned.m8n8.x4.shared.b16 {%0,%1,%2,%3}, [%4];"
            : "=r"(c0), "=r"(c1), "=r"(c2), "=r"(c3) : "r"(bbase + 1024u));

        #define MMA16(NT, B0, B1)                                             \
            asm volatile(                                                      \
                "mma.sync.aligned.m16n8k16.row.col.f32.f16.f16.f32 "           \
                "{%0,%1,%2,%3}, {%4,%5,%6,%7}, {%8,%9}, {%0,%1,%2,%3};"        \
                : "+f"(acc[NT][0]), "+f"(acc[NT][1]),                          \
                  "+f"(acc[NT][2]), "+f"(acc[NT][3])                           \
                : "r"(a0), "r"(a1), "r"(a2), "r"(a3), "r"(B0), "r"(B1))
        #define MMA8(NT, B0)                                                   \
            asm volatile(                                                      \
                "mma.sync.aligned.m16n8k8.row.col.f32.f16.f16.f32 "            \
                "{%0,%1,%2,%3}, {%4,%5}, {%6}, {%0,%1,%2,%3};"                 \
                : "+f"(acc[NT][0]), "+f"(acc[NT][1]),                          \
                  "+f"(acc[NT][2]), "+f"(acc[NT][3])                           \
                : "r"(e0), "r"(e1), "r"(B0))

        MMA16(0, b00, b01); MMA16(1, b10, b11);
        MMA16(2, b20, b21); MMA16(3, b30, b31);
        MMA8(0, c0); MMA8(1, c1); MMA8(2, c2); MMA8(3, c3);
        #undef MMA16
        #undef MMA8
    }

    // ---- epilogue: D rows = pixels (g, g+8), cols = out channels.
    //      Skip stores for pixels with no events (never gathered). ----
    const int g    = lane >> 2;   // 0..7
    const int t4   = lane & 3;    // 0..3
    const int gy   = y0 + ty;
    const int gx1  = x0 + tx + g;
    const int gx2  = gx1 + 8;
    const int sp1  = (ty + 1) * HLX + (tx + g + 1);
    const bool w1  = (gx1 < WW) && (sCnt[sp1] > 0.f);
    const bool w2  = (gx2 < WW) && (sCnt[sp1 + 8] > 0.f);
    #pragma unroll
    for (int nt = 0; nt < 4; nt++) {
        int col = nt * 8 + t4 * 2;
        if (w1)
            *reinterpret_cast<float2*>(
                g_conv + ((size_t)(b * HH + gy) * WW + gx1) * OUT_CH + col) =
                make_float2(acc[nt][0], acc[nt][1]);
        if (w2)
            *reinterpret_cast<float2*>(
                g_conv + ((size_t)(b * HH + gy) * WW + gx2) * OUT_CH + col) =
                make_float2(acc[nt][2], acc[nt][3]);
    }
}

// ---------------------------------------------------------------------------
// 3) Gather: f[i] = conv[key[i]] + bias
//    4 threads/event, each handles 2 independent float4s (MLP=2).
// ---------------------------------------------------------------------------
__global__ void gather_kernel(const float* __restrict__ bias,
                              float* __restrict__ out, int n) {
    int t = blockIdx.x * blockDim.x + threadIdx.x;
    if (t >= n * 4) return;
    int e = t >> 2;
    int q = (t & 3) * 2;          // quad pair: {0,1},{2,3},{4,5},{6,7}
    int key = g_key[e];
    const float4* src = reinterpret_cast<const float4*>(g_conv + (size_t)key * OUT_CH);
    float4 v0 = __ldg(src + q);
    float4 v1 = __ldg(src + q + 1);
    float4 b0 = __ldg(reinterpret_cast<const float4*>(bias) + q);
    float4 b1 = __ldg(reinterpret_cast<const float4*>(bias) + q + 1);
    v0.x += b0.x; v0.y += b0.y; v0.z += b0.z; v0.w += b0.w;
    v1.x += b1.x; v1.y += b1.y; v1.z += b1.z; v1.w += b1.w;
    float4* dst = reinterpret_cast<float4*>(out + (size_t)e * OUT_CH);
    dst[q]     = v0;
    dst[q + 1] = v1;
}

// ---------------------------------------------------------------------------
extern "C" void kernel_launch(void* const* d_in, const int* in_sizes, int n_in,
                              void* d_out, int out_size) {
    // Identify inputs by element count (robust to ordering):
    //   events: N*4, features: N*16, weight: 5184, bias: 32, offsets: 8
    const float* events   = nullptr;
    const float* features = nullptr;
    const float* weight   = nullptr;
    const float* bias     = nullptr;
    const int*   offsets  = nullptr;
    int n = 0, nb = 0;

    int big0 = -1, big1 = -1;
    for (int i = 0; i < n_in; i++) {
        int s = in_sizes[i];
        if (s == WSIZE)            weight  = (const float*)d_in[i];
        else if (s == OUT_CH)      bias    = (const float*)d_in[i];
        else if (s <= 64)        { offsets = (const int*)d_in[i]; nb = s; }
        else if (big0 < 0)         big0 = i;
        else                       big1 = i;
    }
    if (in_sizes[big0] > in_sizes[big1]) { int t = big0; big0 = big1; big1 = t; }
    events   = (const float*)d_in[big0];
    features = (const float*)d_in[big1];
    n = in_sizes[big0] / 4;
    if (nb > BB) nb = BB;

    const int T = 256;

    // opt-in smem for the conv kernel (idempotent host-side config)
    cudaFuncSetAttribute(conv_hmma_kernel,
                         cudaFuncAttributeMaxDynamicSharedMemorySize, DYN_BYTES);

    // 0) zero accumulator
    {
        size_t n4 = (size_t)NPIX * CPAD / 4;
        int blocks = (int)((n4 + T - 1) / T);
        zero_dense_kernel<<<blocks, T>>>();
    }
    // 1) scatter
    scatter_kernel<<<(n + T - 1) / T, T>>>(events, features, offsets, n, nb);
    // 2) conv on fp16 tensor cores (normalization fused into halo staging)
    {
        dim3 grid((WW + TLX - 1) / TLX, HH / TLY, BB);   // 10 x 15 x 8
        conv_hmma_kernel<<<grid, CONV_THREADS, DYN_BYTES>>>(weight);
    }
    // 3) gather + bias
    gather_kernel<<<(n * 4 + T - 1) / T, T>>>(bias, (float*)d_out, n);
}